// round 3
// baseline (speedup 1.0000x reference)
#include <cuda_runtime.h>
#include <math.h>

#define BB 4
#define TT 48
#define NN 2000
#define BN (BB*NN)      // 8000
#define FF 16
#define HH 64
#define NHEADS 4
#define HD 16
#define HOR 24
#define PP 32
#define FT (FF*TT)      // 768

// ---------------- scratch (device globals: no allocation) ----------------
__device__ float g_hT[FT*BN];      // conv features, k-major [768][8000]
__device__ float g_projT[FT*HH];   // proj_w transposed [768][64]
__device__ float g_z[BN*HH];
__device__ float g_node[BN*HH];
__device__ float g_src[BN*PP];
__device__ float g_dst[BN*PP];
__device__ float g_qkv[BN*3*HH];
__device__ float g_yattn[BN*HH];
__device__ float g_y[BN*HH];
__device__ float g_y2[BN*HH];
__device__ unsigned g_maskbits[BB*NN*64];   // 64 words per row

__device__ __forceinline__ float dot4(float4 a, float4 b) {
    return a.x*b.x + a.y*b.y + a.z*b.z + a.w*b.w;
}
__device__ __forceinline__ void cp_async16(void* smem, const void* gmem) {
    unsigned s = (unsigned)__cvta_generic_to_shared(smem);
    asm volatile("cp.async.cg.shared.global [%0], [%1], 16;\n" :: "r"(s), "l"(gmem));
}
__device__ __forceinline__ void cp_commit() { asm volatile("cp.async.commit_group;\n"); }
template<int N> __device__ __forceinline__ void cp_wait() {
    asm volatile("cp.async.wait_group %0;\n" :: "n"(N));
}
__device__ __forceinline__ float4 shfl_xor_f4(float4 v, int m) {
    float4 r;
    r.x = __shfl_xor_sync(0xffffffffu, v.x, m);
    r.y = __shfl_xor_sync(0xffffffffu, v.y, m);
    r.z = __shfl_xor_sync(0xffffffffu, v.z, m);
    r.w = __shfl_xor_sync(0xffffffffu, v.w, m);
    return r;
}

// ---------------- 1) conv1d(SAME,K=3) + BN(eval) + ReLU -> g_hT ----------------
__global__ __launch_bounds__(256) void k_conv(const float* __restrict__ x,
                                              const float* __restrict__ cw,
                                              const float* __restrict__ cb,
                                              const float* __restrict__ bng,
                                              const float* __restrict__ bnb) {
    int node = blockIdx.x * 256 + threadIdx.x;
    int t = blockIdx.y;
    if (node >= BN) return;
    int b = node / NN, n = node - b * NN;
    const float* xb = x + b * (TT * NN) + n;
    float xm1 = (t > 0)      ? xb[(t - 1) * NN] : 0.f;
    float x0  =                xb[t * NN];
    float xp1 = (t < TT - 1) ? xb[(t + 1) * NN] : 0.f;
    float bns = rsqrtf(1.0f + 1e-5f);
#pragma unroll
    for (int f = 0; f < FF; f++) {
        float v = cw[f*3]*xm1 + cw[f*3+1]*x0 + cw[f*3+2]*xp1 + cb[f];
        v = v * (bng[f] * bns) + bnb[f];
        g_hT[(f * TT + t) * BN + node] = fmaxf(v, 0.f);
    }
}

// ---------------- 2) transpose proj_w [64][768] -> [768][64] ----------------
__global__ __launch_bounds__(256) void k_transw(const float* __restrict__ w) {
    int idx = blockIdx.x * 256 + threadIdx.x;
    if (idx < FT * HH) {
        int k = idx >> 6, h = idx & 63;
        g_projT[idx] = w[h * FT + k];
    }
}

// ---------------- 3) z = flat @ proj_w^T + b (tiled SGEMM, double-buffered) ----------------
__global__ __launch_bounds__(256) void k_proj(const float* __restrict__ pb) {
    __shared__ float Asm[2][32][64];
    __shared__ float Bsm[2][32][64];
    int t = threadIdx.x;
    int m0 = blockIdx.x * 64;
    int tx = t & 15, ty = t >> 4;
    int lrow0 = t >> 4, lcol0 = (t & 15) << 2;
    int lrow1 = (t + 256) >> 4, lcol1 = ((t + 256) & 15) << 2;
    float c[4][4] = {};

    const int NT = FT / 32;  // 24
    // prefetch tile 0
    cp_async16(&Asm[0][lrow0][lcol0], &g_hT[lrow0 * BN + m0 + lcol0]);
    cp_async16(&Asm[0][lrow1][lcol1], &g_hT[lrow1 * BN + m0 + lcol1]);
    cp_async16(&Bsm[0][lrow0][lcol0], &g_projT[lrow0 * HH + lcol0]);
    cp_async16(&Bsm[0][lrow1][lcol1], &g_projT[lrow1 * HH + lcol1]);
    cp_commit();

    for (int it = 0; it < NT; it++) {
        if (it + 1 < NT) {
            int k0 = (it + 1) * 32, nb = (it + 1) & 1;
            cp_async16(&Asm[nb][lrow0][lcol0], &g_hT[(k0 + lrow0) * BN + m0 + lcol0]);
            cp_async16(&Asm[nb][lrow1][lcol1], &g_hT[(k0 + lrow1) * BN + m0 + lcol1]);
            cp_async16(&Bsm[nb][lrow0][lcol0], &g_projT[(k0 + lrow0) * HH + lcol0]);
            cp_async16(&Bsm[nb][lrow1][lcol1], &g_projT[(k0 + lrow1) * HH + lcol1]);
            cp_commit();
            cp_wait<1>();
        } else {
            cp_wait<0>();
        }
        __syncthreads();
        int buf = it & 1;
#pragma unroll
        for (int kk = 0; kk < 32; kk++) {
            float4 a  = *(float4*)&Asm[buf][kk][ty * 4];
            float4 b4 = *(float4*)&Bsm[buf][kk][tx * 4];
            float av[4] = {a.x, a.y, a.z, a.w};
            float bv[4] = {b4.x, b4.y, b4.z, b4.w};
#pragma unroll
            for (int i = 0; i < 4; i++)
#pragma unroll
                for (int j = 0; j < 4; j++) c[i][j] += av[i] * bv[j];
        }
        __syncthreads();
    }
#pragma unroll
    for (int i = 0; i < 4; i++) {
        float4 o;
        o.x = c[i][0] + pb[tx*4+0];
        o.y = c[i][1] + pb[tx*4+1];
        o.z = c[i][2] + pb[tx*4+2];
        o.w = c[i][3] + pb[tx*4+3];
        *(float4*)&g_z[(m0 + ty * 4 + i) * HH + tx * 4] = o;
    }
}

// ---------------- 4) LayerNorm + ReLU -> g_node ----------------
__global__ __launch_bounds__(256) void k_ln1(const float* __restrict__ g,
                                             const float* __restrict__ bb) {
    int w = threadIdx.x >> 5, lane = threadIdx.x & 31;
    int m = blockIdx.x * 8 + w;
    float v0 = g_z[m * 64 + lane], v1 = g_z[m * 64 + 32 + lane];
    float s = v0 + v1;
#pragma unroll
    for (int off = 16; off; off >>= 1) s += __shfl_xor_sync(0xffffffffu, s, off);
    float mean = s * (1.f / 64.f);
    float d0 = v0 - mean, d1 = v1 - mean;
    float vs = d0 * d0 + d1 * d1;
#pragma unroll
    for (int off = 16; off; off >>= 1) vs += __shfl_xor_sync(0xffffffffu, vs, off);
    float rs = rsqrtf(vs * (1.f / 64.f) + 1e-5f);
    g_node[m * 64 + lane]      = fmaxf(d0 * rs * g[lane]      + bb[lane],      0.f);
    g_node[m * 64 + 32 + lane] = fmaxf(d1 * rs * g[lane + 32] + bb[lane + 32], 0.f);
}

// ---------------- 5) src/dst (leaky 0.2) + qkv, fused ----------------
__global__ __launch_bounds__(256) void k_sdq(const float* __restrict__ sw, const float* __restrict__ sb,
                                             const float* __restrict__ dw, const float* __restrict__ db,
                                             const float* __restrict__ iw, const float* __restrict__ ib) {
    __shared__ float nsm[64 * 64];
    int t = threadIdx.x;
    int m0 = blockIdx.x * 64;
#pragma unroll
    for (int r = 0; r < 4; r++) {
        int idx = (t + 256 * r) * 4;
        *(float4*)&nsm[idx] = *(const float4*)&g_node[m0 * 64 + idx];
    }
    __syncthreads();
    const float* wrow; float bias;
    if (t < 32)       { wrow = sw + t * 64;        bias = sb[t]; }
    else if (t < 64)  { wrow = dw + (t - 32) * 64; bias = db[t - 32]; }
    else              { wrow = iw + (t - 64) * 64; bias = ib[t - 64]; }
    float4 wr[16];
#pragma unroll
    for (int r = 0; r < 16; r++) wr[r] = *(const float4*)&wrow[r * 4];
    for (int m = 0; m < 64; m++) {
        float acc = bias;
#pragma unroll
        for (int r = 0; r < 16; r++) {
            float4 nv = *(float4*)&nsm[m * 64 + r * 4];
            acc += dot4(wr[r], nv);
        }
        int gm = m0 + m;
        if (t < 64) {
            acc = (acc > 0.f) ? acc : 0.2f * acc;
            if (t < 32) g_src[gm * 32 + t] = acc;
            else        g_dst[gm * 32 + t - 32] = acc;
        } else {
            g_qkv[gm * 192 + t - 64] = acc;
        }
    }
}

// ---------------- 6) attention-1: flash-style, warp per (b,h,q), cp.async double-buffer ----------------
__global__ __launch_bounds__(256) void k_attn1() {
    __shared__ float Ksm[2][128][20];
    __shared__ float Vsm[2][128][20];
    int t = threadIdx.x, w = t >> 5, lane = t & 31;
    int b = blockIdx.z, h = blockIdx.y;
    int q = blockIdx.x * 8 + w;
    const float* qkv_b = g_qkv + b * (NN * 192);
    float4 qr[4];
    {
        const float* qp = qkv_b + q * 192 + h * 16;
#pragma unroll
        for (int r = 0; r < 4; r++) qr[r] = *(const float4*)&qp[r * 4];
    }
    int jld = t >> 1, part = t & 1;
    const int NT = (NN + 127) / 128;  // 16

    auto prefetch = [&](int buf, int j0) {
        int row = j0 + jld;
        if (row > NN - 1) row = NN - 1;
        const float* kp = qkv_b + row * 192 + 64 + h * 16 + part * 8;
        cp_async16(&Ksm[buf][jld][part * 8],     kp);
        cp_async16(&Ksm[buf][jld][part * 8 + 4], kp + 4);
        cp_async16(&Vsm[buf][jld][part * 8],     kp + 64);
        cp_async16(&Vsm[buf][jld][part * 8 + 4], kp + 68);
    };

    prefetch(0, 0); cp_commit();

    float mx = -1e30f, l = 0.f;
    float acc[16] = {};
    for (int it = 0; it < NT; it++) {
        int j0 = it * 128;
        if (it + 1 < NT) { prefetch((it + 1) & 1, j0 + 128); cp_commit(); cp_wait<1>(); }
        else             { cp_wait<0>(); }
        __syncthreads();
        int buf = it & 1;
        float s[4];
#pragma unroll
        for (int c = 0; c < 4; c++) {
            int jj = lane + 32 * c;
            float4 k0 = *(float4*)&Ksm[buf][jj][0];
            float4 k1 = *(float4*)&Ksm[buf][jj][4];
            float4 k2 = *(float4*)&Ksm[buf][jj][8];
            float4 k3 = *(float4*)&Ksm[buf][jj][12];
            float d = dot4(qr[0], k0) + dot4(qr[1], k1) + dot4(qr[2], k2) + dot4(qr[3], k3);
            s[c] = 0.25f * d;
            if (j0 + jj >= NN) s[c] = -1e30f;
        }
        float tmax = fmaxf(fmaxf(s[0], s[1]), fmaxf(s[2], s[3]));
#pragma unroll
        for (int off = 16; off; off >>= 1) tmax = fmaxf(tmax, __shfl_xor_sync(0xffffffffu, tmax, off));
        if (tmax > mx) {
            float f = __expf(mx - tmax);
            l *= f;
#pragma unroll
            for (int d = 0; d < 16; d++) acc[d] *= f;
            mx = tmax;
        }
#pragma unroll
        for (int c = 0; c < 4; c++) {
            float p = __expf(s[c] - mx);
            l += p;
            int jj = lane + 32 * c;
            float4 v0 = *(float4*)&Vsm[buf][jj][0];
            float4 v1 = *(float4*)&Vsm[buf][jj][4];
            float4 v2 = *(float4*)&Vsm[buf][jj][8];
            float4 v3 = *(float4*)&Vsm[buf][jj][12];
            acc[0]+=p*v0.x; acc[1]+=p*v0.y; acc[2]+=p*v0.z; acc[3]+=p*v0.w;
            acc[4]+=p*v1.x; acc[5]+=p*v1.y; acc[6]+=p*v1.z; acc[7]+=p*v1.w;
            acc[8]+=p*v2.x; acc[9]+=p*v2.y; acc[10]+=p*v2.z; acc[11]+=p*v2.w;
            acc[12]+=p*v3.x; acc[13]+=p*v3.y; acc[14]+=p*v3.z; acc[15]+=p*v3.w;
        }
        __syncthreads();
    }
#pragma unroll
    for (int off = 16; off; off >>= 1) {
        l += __shfl_xor_sync(0xffffffffu, l, off);
#pragma unroll
        for (int d = 0; d < 16; d++) acc[d] += __shfl_xor_sync(0xffffffffu, acc[d], off);
    }
    if (lane == 0) {
        float inv = 1.f / l;
        float* op = g_yattn + (b * NN + q) * 64 + h * 16;
#pragma unroll
        for (int r = 0; r < 4; r++) {
            float4 o = make_float4(acc[4*r]*inv, acc[4*r+1]*inv, acc[4*r+2]*inv, acc[4*r+3]*inv);
            *(float4*)&op[r * 4] = o;
        }
    }
}

// ---------------- 7) out projection y = y_attn @ out_w^T + out_b ----------------
__global__ __launch_bounds__(256) void k_outp(const float* __restrict__ ow,
                                              const float* __restrict__ ob) {
    __shared__ float ysm[64 * 64];
    int t = threadIdx.x;
    int m0 = blockIdx.x * 64;
#pragma unroll
    for (int r = 0; r < 4; r++) {
        int idx = (t + 256 * r) * 4;
        *(float4*)&ysm[idx] = *(const float4*)&g_yattn[m0 * 64 + idx];
    }
    __syncthreads();
    int o = t & 63, gq = t >> 6;
    float4 wr[16];
#pragma unroll
    for (int r = 0; r < 16; r++) wr[r] = *(const float4*)&ow[o * 64 + r * 4];
    float bias = ob[o];
    for (int rr = 0; rr < 16; rr++) {
        int mm = gq * 16 + rr;
        float acc = bias;
#pragma unroll
        for (int r = 0; r < 16; r++) {
            float4 nv = *(float4*)&ysm[mm * 64 + r * 4];
            acc += dot4(wr[r], nv);
        }
        g_y[(m0 + mm) * 64 + o] = acc;
    }
}

// ---------------- 8) adjacency mask bits (norm pass + ballot pass, cp.async) ----------------
__global__ __launch_bounds__(256) void k_mask(const float* __restrict__ es) {
    __shared__ float ssm[32][36];
    __shared__ float dsm[2][64][36];
    __shared__ float normsm[32];
    int t = threadIdx.x, w = t >> 5, lane = t & 31;
    int b = blockIdx.y;
    int q0 = blockIdx.x * 32;
    float scale = es[0];
    {
        int row = t >> 3, col = (t & 7) << 2;
        int q = q0 + row;
        float4 v = make_float4(0.f, 0.f, 0.f, 0.f);
        if (q < NN) v = *(const float4*)&g_src[(b * NN + q) * 32 + col];
        *(float4*)&ssm[row][col] = v;
    }
    int lrow0 = t >> 3, lcol0 = (t & 7) << 2;
    int lrow1 = (t + 256) >> 3, lcol1 = ((t + 256) & 7) << 2;
    auto prefetch = [&](int buf, int j0) {
        int r0 = j0 + lrow0; if (r0 > NN - 1) r0 = NN - 1;
        int r1 = j0 + lrow1; if (r1 > NN - 1) r1 = NN - 1;
        cp_async16(&dsm[buf][lrow0][lcol0], &g_dst[(b * NN + r0) * 32 + lcol0]);
        cp_async16(&dsm[buf][lrow1][lcol1], &g_dst[(b * NN + r1) * 32 + lcol1]);
    };

    const int NJT = 32;
    // ---------------- pass 1: row norms ----------------
    prefetch(0, 0); cp_commit();
    float sumsq[4] = {};
    for (int jt = 0; jt < NJT; jt++) {
        int j0 = jt * 64;
        if (jt + 1 < NJT) { prefetch((jt + 1) & 1, j0 + 64); cp_commit(); cp_wait<1>(); }
        else              { cp_wait<0>(); }
        __syncthreads();
        int buf = jt & 1;
#pragma unroll
        for (int c = 0; c < 4; c++) {
            int qq = w * 4 + c;
            float4 qv[8];
#pragma unroll
            for (int r = 0; r < 8; r++) qv[r] = *(float4*)&ssm[qq][r * 4];
#pragma unroll
            for (int half = 0; half < 2; half++) {
                int jj = lane + 32 * half;
                float s = 0.f;
#pragma unroll
                for (int r = 0; r < 8; r++) s += dot4(qv[r], *(float4*)&dsm[buf][jj][r * 4]);
                if (j0 + jj < NN) sumsq[c] += s * s;
            }
        }
        __syncthreads();
    }
#pragma unroll
    for (int c = 0; c < 4; c++) {
        float red = sumsq[c];
#pragma unroll
        for (int off = 16; off; off >>= 1) red += __shfl_xor_sync(0xffffffffu, red, off);
        if (lane == 0) normsm[w * 4 + c] = fmaxf(sqrtf(red) * fabsf(scale), 1e-12f);
    }
    __syncthreads();
    // ---------------- pass 2: ballot mask bits ----------------
    prefetch(0, 0); cp_commit();
    for (int jt = 0; jt < NJT; jt++) {
        int j0 = jt * 64;
        if (jt + 1 < NJT) { prefetch((jt + 1) & 1, j0 + 64); cp_commit(); cp_wait<1>(); }
        else              { cp_wait<0>(); }
        __syncthreads();
        int buf = jt & 1;
#pragma unroll
        for (int c = 0; c < 4; c++) {
            int qq = w * 4 + c;
            int q = q0 + qq;
            float inv = scale / normsm[qq];
            float4 qv[8];
#pragma unroll
            for (int r = 0; r < 8; r++) qv[r] = *(float4*)&ssm[qq][r * 4];
#pragma unroll
            for (int half = 0; half < 2; half++) {
                int jj = lane + 32 * half;
                float s = 0.f;
#pragma unroll
                for (int r = 0; r < 8; r++) s += dot4(qv[r], *(float4*)&dsm[buf][jj][r * 4]);
                float val = s * inv + ((j0 + jj) == q ? 1.f : 0.f);
                unsigned word = __ballot_sync(0xffffffffu, val <= 0.f);
                if (lane == 0 && q < NN) g_maskbits[(b * NN + q) * 64 + jt * 2 + half] = word;
            }
        }
        __syncthreads();
    }
}

// ---------------- 9) attention-2 (adjacency-masked), lane-owns-keys, cp.async ----------------
__global__ __launch_bounds__(256) void k_attn2() {
    __shared__ float ysm[2][64][68];
    __shared__ float qsm[8][68];
    int t = threadIdx.x, w = t >> 5, lane = t & 31;
    int b = blockIdx.y;
    int q = blockIdx.x * 8 + w;
    const float* yb = g_y + b * (NN * 64);
    const unsigned* mrow = g_maskbits + (b * NN + q) * 64;
    // load this warp's query row into qsm[w]
    *(float2*)&qsm[w][2 * lane] = *(const float2*)&yb[q * 64 + 2 * lane];

    int lrow0 = t >> 4, lcol0 = (t & 15) << 2;
    auto prefetch = [&](int buf, int j0) {
#pragma unroll
        for (int r = 0; r < 4; r++) {
            int row = lrow0 + 16 * r;
            int grow = j0 + row; if (grow > NN - 1) grow = NN - 1;
            cp_async16(&ysm[buf][row][lcol0], &yb[grow * 64 + lcol0]);
        }
    };

    const int NT = (NN + 63) / 64;  // 32
    prefetch(0, 0); cp_commit();

    float mx = -1e30f, lsum = 0.f;
    float4 acc4[16];
#pragma unroll
    for (int r = 0; r < 16; r++) acc4[r] = make_float4(0.f, 0.f, 0.f, 0.f);

    for (int it = 0; it < NT; it++) {
        int j0 = it * 64;
        if (it + 1 < NT) { prefetch((it + 1) & 1, j0 + 64); cp_commit(); cp_wait<1>(); }
        else             { cp_wait<0>(); }
        __syncthreads();
        int buf = it & 1;
        unsigned w0 = mrow[it * 2];
        unsigned w1 = mrow[it * 2 + 1];
        float s0 = 0.f, s1 = 0.f;
#pragma unroll
        for (int r = 0; r < 16; r++) {
            float4 qv = *(float4*)&qsm[w][r * 4];
            float4 k0 = *(float4*)&ysm[buf][lane][r * 4];
            float4 k1 = *(float4*)&ysm[buf][lane + 32][r * 4];
            s0 += dot4(qv, k0);
            s1 += dot4(qv, k1);
        }
        s0 = s0 * 0.125f + (((w0 >> lane) & 1u) ? -1e9f : 0.f);
        s1 = s1 * 0.125f + (((w1 >> lane) & 1u) ? -1e9f : 0.f);
        if (j0 + lane >= NN)      s0 = -1e30f;
        if (j0 + 32 + lane >= NN) s1 = -1e30f;
        float tmax = fmaxf(s0, s1);
#pragma unroll
        for (int off = 16; off; off >>= 1) tmax = fmaxf(tmax, __shfl_xor_sync(0xffffffffu, tmax, off));
        if (tmax > mx) {
            float f = __expf(mx - tmax);
            lsum *= f;
#pragma unroll
            for (int r = 0; r < 16; r++) {
                acc4[r].x *= f; acc4[r].y *= f; acc4[r].z *= f; acc4[r].w *= f;
            }
            mx = tmax;
        }
        float p0 = __expf(s0 - mx), p1 = __expf(s1 - mx);
        lsum += p0 + p1;
#pragma unroll
        for (int r = 0; r < 16; r++) {
            float4 v0 = *(float4*)&ysm[buf][lane][r * 4];
            float4 v1 = *(float4*)&ysm[buf][lane + 32][r * 4];
            acc4[r].x += p0 * v0.x + p1 * v1.x;
            acc4[r].y += p0 * v0.y + p1 * v1.y;
            acc4[r].z += p0 * v0.z + p1 * v1.z;
            acc4[r].w += p0 * v0.w + p1 * v1.w;
        }
        __syncthreads();
    }
    // total normalizer
#pragma unroll
    for (int off = 16; off; off >>= 1) lsum += __shfl_xor_sync(0xffffffffu, lsum, off);
    float inv = 1.f / lsum;
    // halving butterfly: lane ends owning dims 2*lane, 2*lane+1
#pragma unroll
    for (int r = 0; r < 8; r++) {
        float4 send = (lane & 16) ? acc4[r] : acc4[r + 8];
        float4 oth = shfl_xor_f4(send, 16);
        float4 keep = (lane & 16) ? acc4[r + 8] : acc4[r];
        acc4[r] = make_float4(keep.x + oth.x, keep.y + oth.y, keep.z + oth.z, keep.w + oth.w);
    }
#pragma unroll
    for (int r = 0; r < 4; r++) {
        float4 send = (lane & 8) ? acc4[r] : acc4[r + 4];
        float4 oth = shfl_xor_f4(send, 8);
        float4 keep = (lane & 8) ? acc4[r + 4] : acc4[r];
        acc4[r] = make_float4(keep.x + oth.x, keep.y + oth.y, keep.z + oth.z, keep.w + oth.w);
    }
#pragma unroll
    for (int r = 0; r < 2; r++) {
        float4 send = (lane & 4) ? acc4[r] : acc4[r + 2];
        float4 oth = shfl_xor_f4(send, 4);
        float4 keep = (lane & 4) ? acc4[r + 2] : acc4[r];
        acc4[r] = make_float4(keep.x + oth.x, keep.y + oth.y, keep.z + oth.z, keep.w + oth.w);
    }
    {
        float4 send = (lane & 2) ? acc4[0] : acc4[1];
        float4 oth = shfl_xor_f4(send, 2);
        float4 keep = (lane & 2) ? acc4[1] : acc4[0];
        acc4[0] = make_float4(keep.x + oth.x, keep.y + oth.y, keep.z + oth.z, keep.w + oth.w);
    }
    {
        float2 send = (lane & 1) ? make_float2(acc4[0].x, acc4[0].y) : make_float2(acc4[0].z, acc4[0].w);
        float2 oth;
        oth.x = __shfl_xor_sync(0xffffffffu, send.x, 1);
        oth.y = __shfl_xor_sync(0xffffffffu, send.y, 1);
        float2 keep = (lane & 1) ? make_float2(acc4[0].z, acc4[0].w) : make_float2(acc4[0].x, acc4[0].y);
        float2 res = make_float2((keep.x + oth.x) * inv, (keep.y + oth.y) * inv);
        *(float2*)&g_y2[(b * NN + q) * 64 + 2 * lane] = res;
    }
}

// ---------------- 10) residual + LN(lnA) + horizon predictor ----------------
__global__ __launch_bounds__(256) void k_final(const float* __restrict__ lg,
                                               const float* __restrict__ lb,
                                               const float* __restrict__ pw,
                                               const float* __restrict__ pb,
                                               float* __restrict__ out) {
    __shared__ float rsm[8][64];
    __shared__ float pwsm[64 * 24];
    int t = threadIdx.x, w = t >> 5, lane = t & 31;
    int m = blockIdx.x * 8 + w;
    for (int idx = t; idx < 24 * 64; idx += 256) {
        int o = idx >> 6, d = idx & 63;
        pwsm[d * 24 + o] = pw[idx];
    }
    float v0 = g_y2[m * 64 + lane]      + g_node[m * 64 + lane];
    float v1 = g_y2[m * 64 + 32 + lane] + g_node[m * 64 + 32 + lane];
    float s = v0 + v1;
#pragma unroll
    for (int off = 16; off; off >>= 1) s += __shfl_xor_sync(0xffffffffu, s, off);
    float mean = s * (1.f / 64.f);
    float d0 = v0 - mean, d1 = v1 - mean;
    float vs = d0 * d0 + d1 * d1;
#pragma unroll
    for (int off = 16; off; off >>= 1) vs += __shfl_xor_sync(0xffffffffu, vs, off);
    float rs = rsqrtf(vs * (1.f / 64.f) + 1e-5f);
    rsm[w][lane]      = d0 * rs * lg[lane]      + lb[lane];
    rsm[w][lane + 32] = d1 * rs * lg[lane + 32] + lb[lane + 32];
    __syncthreads();
    if (lane < 24) {
        float acc = pb[lane];
#pragma unroll
        for (int d = 0; d < 64; d++) acc += rsm[w][d] * pwsm[d * 24 + lane];
        out[m * 24 + lane] = acc;
    }
}

// ---------------- launch ----------------
extern "C" void kernel_launch(void* const* d_in, const int* in_sizes, int n_in,
                              void* d_out, int out_size) {
    const float* x        = (const float*)d_in[0];
    const float* conv_w   = (const float*)d_in[1];
    const float* conv_b   = (const float*)d_in[2];
    const float* bn_g     = (const float*)d_in[3];
    const float* bn_b     = (const float*)d_in[4];
    const float* proj_w   = (const float*)d_in[5];
    const float* proj_b   = (const float*)d_in[6];
    const float* ln1_g    = (const float*)d_in[7];
    const float* ln1_b    = (const float*)d_in[8];
    const float* src_w    = (const float*)d_in[9];
    const float* src_b    = (const float*)d_in[10];
    const float* dst_w    = (const float*)d_in[11];
    const float* dst_b    = (const float*)d_in[12];
    const float* edge_sc  = (const float*)d_in[13];
    const float* inp_w    = (const float*)d_in[14];
    const float* inp_b    = (const float*)d_in[15];
    const float* out_w    = (const float*)d_in[16];
    const float* out_b    = (const float*)d_in[17];
    const float* lnA_g    = (const float*)d_in[18];
    const float* lnA_b    = (const float*)d_in[19];
    const float* pred_w   = (const float*)d_in[20];
    const float* pred_b   = (const float*)d_in[21];
    float* out = (float*)d_out;

    k_conv<<<dim3((BN + 255) / 256, TT), 256>>>(x, conv_w, conv_b, bn_g, bn_b);
    k_transw<<<(FT * HH + 255) / 256, 256>>>(proj_w);
    k_proj<<<BN / 64, 256>>>(proj_b);
    k_ln1<<<BN / 8, 256>>>(ln1_g, ln1_b);
    k_sdq<<<BN / 64, 256>>>(src_w, src_b, dst_w, dst_b, inp_w, inp_b);
    k_attn1<<<dim3(NN / 8, NHEADS, BB), 256>>>();
    k_outp<<<BN / 64, 256>>>(out_w, out_b);
    k_mask<<<dim3((NN + 31) / 32, BB), 256>>>(edge_sc);
    k_attn2<<<dim3(NN / 8, BB), 256>>>();
    k_final<<<BN / 8, 256>>>(lnA_g, lnA_b, pred_w, pred_b, out);
}

// round 4
// speedup vs baseline: 1.8308x; 1.8308x over previous
#include <cuda_runtime.h>
#include <math.h>

#define BB 4
#define TT 48
#define NN 2000
#define BN (BB*NN)      // 8000
#define FF 16
#define HH 64
#define NHEADS 4
#define HD 16
#define HOR 24
#define PP 32
#define FT (FF*TT)      // 768

// ---------------- scratch (device globals: no allocation) ----------------
__device__ float g_hT[FT*BN];      // conv features, k-major [768][8000]
__device__ float g_projT[FT*HH];   // proj_w transposed [768][64]
__device__ float g_z[BN*HH];
__device__ float g_node[BN*HH];
__device__ float g_src[BN*PP];
__device__ float g_dst[BN*PP];
__device__ float g_qkv[BN*3*HH];
__device__ float g_yattn[BN*HH];
__device__ float g_y[BN*HH];
__device__ float g_y2[BN*HH];
__device__ unsigned g_maskbits[BB*NN*64];   // 64 words per row

__device__ __forceinline__ float dot4(float4 a, float4 b) {
    return a.x*b.x + a.y*b.y + a.z*b.z + a.w*b.w;
}
__device__ __forceinline__ void cp_async16(void* smem, const void* gmem) {
    unsigned s = (unsigned)__cvta_generic_to_shared(smem);
    asm volatile("cp.async.cg.shared.global [%0], [%1], 16;\n" :: "r"(s), "l"(gmem));
}
__device__ __forceinline__ void cp_commit() { asm volatile("cp.async.commit_group;\n"); }
template<int N> __device__ __forceinline__ void cp_wait() {
    asm volatile("cp.async.wait_group %0;\n" :: "n"(N));
}
__device__ __forceinline__ float4 shfl_xor_f4(float4 v, int m) {
    float4 r;
    r.x = __shfl_xor_sync(0xffffffffu, v.x, m);
    r.y = __shfl_xor_sync(0xffffffffu, v.y, m);
    r.z = __shfl_xor_sync(0xffffffffu, v.z, m);
    r.w = __shfl_xor_sync(0xffffffffu, v.w, m);
    return r;
}

// ---------------- 1) conv1d(SAME,K=3) + BN(eval) + ReLU -> g_hT ----------------
__global__ __launch_bounds__(256) void k_conv(const float* __restrict__ x,
                                              const float* __restrict__ cw,
                                              const float* __restrict__ cb,
                                              const float* __restrict__ bng,
                                              const float* __restrict__ bnb) {
    int node = blockIdx.x * 256 + threadIdx.x;
    int t = blockIdx.y;
    if (node >= BN) return;
    int b = node / NN, n = node - b * NN;
    const float* xb = x + b * (TT * NN) + n;
    float xm1 = (t > 0)      ? xb[(t - 1) * NN] : 0.f;
    float x0  =                xb[t * NN];
    float xp1 = (t < TT - 1) ? xb[(t + 1) * NN] : 0.f;
    float bns = rsqrtf(1.0f + 1e-5f);
#pragma unroll
    for (int f = 0; f < FF; f++) {
        float v = cw[f*3]*xm1 + cw[f*3+1]*x0 + cw[f*3+2]*xp1 + cb[f];
        v = v * (bng[f] * bns) + bnb[f];
        g_hT[(f * TT + t) * BN + node] = fmaxf(v, 0.f);
    }
}

// ---------------- 2) transpose proj_w [64][768] -> [768][64] ----------------
__global__ __launch_bounds__(256) void k_transw(const float* __restrict__ w) {
    int idx = blockIdx.x * 256 + threadIdx.x;
    if (idx < FT * HH) {
        int k = idx >> 6, h = idx & 63;
        g_projT[idx] = w[h * FT + k];
    }
}

// ---------------- 3) z = flat @ proj_w^T + b (tiled SGEMM, double-buffered) ----------------
__global__ __launch_bounds__(256) void k_proj(const float* __restrict__ pb) {
    __shared__ float Asm[2][32][64];
    __shared__ float Bsm[2][32][64];
    int t = threadIdx.x;
    int m0 = blockIdx.x * 64;
    int tx = t & 15, ty = t >> 4;
    int lrow0 = t >> 4, lcol0 = (t & 15) << 2;
    int lrow1 = (t + 256) >> 4, lcol1 = ((t + 256) & 15) << 2;
    float c[4][4] = {};

    const int NT = FT / 32;  // 24
    cp_async16(&Asm[0][lrow0][lcol0], &g_hT[lrow0 * BN + m0 + lcol0]);
    cp_async16(&Asm[0][lrow1][lcol1], &g_hT[lrow1 * BN + m0 + lcol1]);
    cp_async16(&Bsm[0][lrow0][lcol0], &g_projT[lrow0 * HH + lcol0]);
    cp_async16(&Bsm[0][lrow1][lcol1], &g_projT[lrow1 * HH + lcol1]);
    cp_commit();

    for (int it = 0; it < NT; it++) {
        if (it + 1 < NT) {
            int k0 = (it + 1) * 32, nb = (it + 1) & 1;
            cp_async16(&Asm[nb][lrow0][lcol0], &g_hT[(k0 + lrow0) * BN + m0 + lcol0]);
            cp_async16(&Asm[nb][lrow1][lcol1], &g_hT[(k0 + lrow1) * BN + m0 + lcol1]);
            cp_async16(&Bsm[nb][lrow0][lcol0], &g_projT[(k0 + lrow0) * HH + lcol0]);
            cp_async16(&Bsm[nb][lrow1][lcol1], &g_projT[(k0 + lrow1) * HH + lcol1]);
            cp_commit();
            cp_wait<1>();
        } else {
            cp_wait<0>();
        }
        __syncthreads();
        int buf = it & 1;
#pragma unroll
        for (int kk = 0; kk < 32; kk++) {
            float4 a  = *(float4*)&Asm[buf][kk][ty * 4];
            float4 b4 = *(float4*)&Bsm[buf][kk][tx * 4];
            float av[4] = {a.x, a.y, a.z, a.w};
            float bv[4] = {b4.x, b4.y, b4.z, b4.w};
#pragma unroll
            for (int i = 0; i < 4; i++)
#pragma unroll
                for (int j = 0; j < 4; j++) c[i][j] += av[i] * bv[j];
        }
        __syncthreads();
    }
#pragma unroll
    for (int i = 0; i < 4; i++) {
        float4 o;
        o.x = c[i][0] + pb[tx*4+0];
        o.y = c[i][1] + pb[tx*4+1];
        o.z = c[i][2] + pb[tx*4+2];
        o.w = c[i][3] + pb[tx*4+3];
        *(float4*)&g_z[(m0 + ty * 4 + i) * HH + tx * 4] = o;
    }
}

// ---------------- 4) LayerNorm + ReLU -> g_node ----------------
__global__ __launch_bounds__(256) void k_ln1(const float* __restrict__ g,
                                             const float* __restrict__ bb) {
    int w = threadIdx.x >> 5, lane = threadIdx.x & 31;
    int m = blockIdx.x * 8 + w;
    float v0 = g_z[m * 64 + lane], v1 = g_z[m * 64 + 32 + lane];
    float s = v0 + v1;
#pragma unroll
    for (int off = 16; off; off >>= 1) s += __shfl_xor_sync(0xffffffffu, s, off);
    float mean = s * (1.f / 64.f);
    float d0 = v0 - mean, d1 = v1 - mean;
    float vs = d0 * d0 + d1 * d1;
#pragma unroll
    for (int off = 16; off; off >>= 1) vs += __shfl_xor_sync(0xffffffffu, vs, off);
    float rs = rsqrtf(vs * (1.f / 64.f) + 1e-5f);
    g_node[m * 64 + lane]      = fmaxf(d0 * rs * g[lane]      + bb[lane],      0.f);
    g_node[m * 64 + 32 + lane] = fmaxf(d1 * rs * g[lane + 32] + bb[lane + 32], 0.f);
}

// ---------------- 5) src/dst (leaky 0.2) + qkv, fused ----------------
__global__ __launch_bounds__(256) void k_sdq(const float* __restrict__ sw, const float* __restrict__ sb,
                                             const float* __restrict__ dw, const float* __restrict__ db,
                                             const float* __restrict__ iw, const float* __restrict__ ib) {
    __shared__ float nsm[64 * 64];
    int t = threadIdx.x;
    int m0 = blockIdx.x * 64;
#pragma unroll
    for (int r = 0; r < 4; r++) {
        int idx = (t + 256 * r) * 4;
        *(float4*)&nsm[idx] = *(const float4*)&g_node[m0 * 64 + idx];
    }
    __syncthreads();
    const float* wrow; float bias;
    if (t < 32)       { wrow = sw + t * 64;        bias = sb[t]; }
    else if (t < 64)  { wrow = dw + (t - 32) * 64; bias = db[t - 32]; }
    else              { wrow = iw + (t - 64) * 64; bias = ib[t - 64]; }
    float4 wr[16];
#pragma unroll
    for (int r = 0; r < 16; r++) wr[r] = *(const float4*)&wrow[r * 4];
    for (int m = 0; m < 64; m++) {
        float acc = bias;
#pragma unroll
        for (int r = 0; r < 16; r++) {
            float4 nv = *(float4*)&nsm[m * 64 + r * 4];
            acc += dot4(wr[r], nv);
        }
        int gm = m0 + m;
        if (t < 64) {
            acc = (acc > 0.f) ? acc : 0.2f * acc;
            if (t < 32) g_src[gm * 32 + t] = acc;
            else        g_dst[gm * 32 + t - 32] = acc;
        } else {
            g_qkv[gm * 192 + t - 64] = acc;
        }
    }
}

// ---------------- 6) attention-1: 2 queries per warp, cp.async double-buffer ----------------
__global__ __launch_bounds__(256) void k_attn1() {
    __shared__ float Ksm[2][128][20];
    __shared__ float Vsm[2][128][20];
    int t = threadIdx.x, w = t >> 5, lane = t & 31;
    int b = blockIdx.z, h = blockIdx.y;
    int q0 = blockIdx.x * 16 + w * 2;   // queries q0, q0+1
    const float* qkv_b = g_qkv + b * (NN * 192);
    float4 qr[2][4];
#pragma unroll
    for (int qq = 0; qq < 2; qq++) {
        const float* qp = qkv_b + (q0 + qq) * 192 + h * 16;
#pragma unroll
        for (int r = 0; r < 4; r++) qr[qq][r] = *(const float4*)&qp[r * 4];
    }
    int jld = t >> 1, part = t & 1;
    const int NT = (NN + 127) / 128;  // 16

    auto prefetch = [&](int buf, int j0) {
        int row = j0 + jld;
        if (row > NN - 1) row = NN - 1;
        const float* kp = qkv_b + row * 192 + 64 + h * 16 + part * 8;
        cp_async16(&Ksm[buf][jld][part * 8],     kp);
        cp_async16(&Ksm[buf][jld][part * 8 + 4], kp + 4);
        cp_async16(&Vsm[buf][jld][part * 8],     kp + 64);
        cp_async16(&Vsm[buf][jld][part * 8 + 4], kp + 68);
    };

    prefetch(0, 0); cp_commit();

    float mx0 = -1e30f, l0 = 0.f, mx1 = -1e30f, l1 = 0.f;
    float acc0[16] = {}, acc1[16] = {};
    for (int it = 0; it < NT; it++) {
        int j0 = it * 128;
        if (it + 1 < NT) { prefetch((it + 1) & 1, j0 + 128); cp_commit(); cp_wait<1>(); }
        else             { cp_wait<0>(); }
        __syncthreads();
        int buf = it & 1;
        float s0[4], s1[4];
#pragma unroll
        for (int c = 0; c < 4; c++) {
            int jj = lane + 32 * c;
            float4 k0 = *(float4*)&Ksm[buf][jj][0];
            float4 k1 = *(float4*)&Ksm[buf][jj][4];
            float4 k2 = *(float4*)&Ksm[buf][jj][8];
            float4 k3 = *(float4*)&Ksm[buf][jj][12];
            float dA = dot4(qr[0][0], k0) + dot4(qr[0][1], k1) + dot4(qr[0][2], k2) + dot4(qr[0][3], k3);
            float dB = dot4(qr[1][0], k0) + dot4(qr[1][1], k1) + dot4(qr[1][2], k2) + dot4(qr[1][3], k3);
            bool oob = (j0 + jj >= NN);
            s0[c] = oob ? -1e30f : 0.25f * dA;
            s1[c] = oob ? -1e30f : 0.25f * dB;
        }
        float t0 = fmaxf(fmaxf(s0[0], s0[1]), fmaxf(s0[2], s0[3]));
        float t1 = fmaxf(fmaxf(s1[0], s1[1]), fmaxf(s1[2], s1[3]));
#pragma unroll
        for (int off = 16; off; off >>= 1) {
            t0 = fmaxf(t0, __shfl_xor_sync(0xffffffffu, t0, off));
            t1 = fmaxf(t1, __shfl_xor_sync(0xffffffffu, t1, off));
        }
        if (t0 > mx0) {
            float f = __expf(mx0 - t0);
            l0 *= f;
#pragma unroll
            for (int d = 0; d < 16; d++) acc0[d] *= f;
            mx0 = t0;
        }
        if (t1 > mx1) {
            float f = __expf(mx1 - t1);
            l1 *= f;
#pragma unroll
            for (int d = 0; d < 16; d++) acc1[d] *= f;
            mx1 = t1;
        }
#pragma unroll
        for (int c = 0; c < 4; c++) {
            float p0 = __expf(s0[c] - mx0);
            float p1 = __expf(s1[c] - mx1);
            l0 += p0; l1 += p1;
            int jj = lane + 32 * c;
            float4 v0 = *(float4*)&Vsm[buf][jj][0];
            float4 v1 = *(float4*)&Vsm[buf][jj][4];
            float4 v2 = *(float4*)&Vsm[buf][jj][8];
            float4 v3 = *(float4*)&Vsm[buf][jj][12];
            acc0[0]+=p0*v0.x; acc0[1]+=p0*v0.y; acc0[2]+=p0*v0.z; acc0[3]+=p0*v0.w;
            acc0[4]+=p0*v1.x; acc0[5]+=p0*v1.y; acc0[6]+=p0*v1.z; acc0[7]+=p0*v1.w;
            acc0[8]+=p0*v2.x; acc0[9]+=p0*v2.y; acc0[10]+=p0*v2.z; acc0[11]+=p0*v2.w;
            acc0[12]+=p0*v3.x; acc0[13]+=p0*v3.y; acc0[14]+=p0*v3.z; acc0[15]+=p0*v3.w;
            acc1[0]+=p1*v0.x; acc1[1]+=p1*v0.y; acc1[2]+=p1*v0.z; acc1[3]+=p1*v0.w;
            acc1[4]+=p1*v1.x; acc1[5]+=p1*v1.y; acc1[6]+=p1*v1.z; acc1[7]+=p1*v1.w;
            acc1[8]+=p1*v2.x; acc1[9]+=p1*v2.y; acc1[10]+=p1*v2.z; acc1[11]+=p1*v2.w;
            acc1[12]+=p1*v3.x; acc1[13]+=p1*v3.y; acc1[14]+=p1*v3.z; acc1[15]+=p1*v3.w;
        }
        __syncthreads();
    }
#pragma unroll
    for (int off = 16; off; off >>= 1) {
        l0 += __shfl_xor_sync(0xffffffffu, l0, off);
        l1 += __shfl_xor_sync(0xffffffffu, l1, off);
#pragma unroll
        for (int d = 0; d < 16; d++) {
            acc0[d] += __shfl_xor_sync(0xffffffffu, acc0[d], off);
            acc1[d] += __shfl_xor_sync(0xffffffffu, acc1[d], off);
        }
    }
    if (lane == 0) {
        float inv0 = 1.f / l0, inv1 = 1.f / l1;
        float* op0 = g_yattn + (b * NN + q0) * 64 + h * 16;
        float* op1 = g_yattn + (b * NN + q0 + 1) * 64 + h * 16;
#pragma unroll
        for (int r = 0; r < 4; r++) {
            *(float4*)&op0[r * 4] = make_float4(acc0[4*r]*inv0, acc0[4*r+1]*inv0, acc0[4*r+2]*inv0, acc0[4*r+3]*inv0);
            *(float4*)&op1[r * 4] = make_float4(acc1[4*r]*inv1, acc1[4*r+1]*inv1, acc1[4*r+2]*inv1, acc1[4*r+3]*inv1);
        }
    }
}

// ---------------- 7) out projection y = y_attn @ out_w^T + out_b ----------------
__global__ __launch_bounds__(256) void k_outp(const float* __restrict__ ow,
                                              const float* __restrict__ ob) {
    __shared__ float ysm[64 * 64];
    int t = threadIdx.x;
    int m0 = blockIdx.x * 64;
#pragma unroll
    for (int r = 0; r < 4; r++) {
        int idx = (t + 256 * r) * 4;
        *(float4*)&ysm[idx] = *(const float4*)&g_yattn[m0 * 64 + idx];
    }
    __syncthreads();
    int o = t & 63, gq = t >> 6;
    float4 wr[16];
#pragma unroll
    for (int r = 0; r < 16; r++) wr[r] = *(const float4*)&ow[o * 64 + r * 4];
    float bias = ob[o];
    for (int rr = 0; rr < 16; rr++) {
        int mm = gq * 16 + rr;
        float acc = bias;
#pragma unroll
        for (int r = 0; r < 16; r++) {
            float4 nv = *(float4*)&ysm[mm * 64 + r * 4];
            acc += dot4(wr[r], nv);
        }
        g_y[(m0 + mm) * 64 + o] = acc;
    }
}

// ---------------- 8) adjacency mask bits (norm pass + ballot pass, cp.async) ----------------
__global__ __launch_bounds__(256) void k_mask(const float* __restrict__ es) {
    __shared__ float ssm[32][36];
    __shared__ float dsm[2][64][36];
    __shared__ float normsm[32];
    int t = threadIdx.x, w = t >> 5, lane = t & 31;
    int b = blockIdx.y;
    int q0 = blockIdx.x * 32;
    float scale = es[0];
    {
        int row = t >> 3, col = (t & 7) << 2;
        int q = q0 + row;
        float4 v = make_float4(0.f, 0.f, 0.f, 0.f);
        if (q < NN) v = *(const float4*)&g_src[(b * NN + q) * 32 + col];
        *(float4*)&ssm[row][col] = v;
    }
    int lrow0 = t >> 3, lcol0 = (t & 7) << 2;
    int lrow1 = (t + 256) >> 3, lcol1 = ((t + 256) & 7) << 2;
    auto prefetch = [&](int buf, int j0) {
        int r0 = j0 + lrow0; if (r0 > NN - 1) r0 = NN - 1;
        int r1 = j0 + lrow1; if (r1 > NN - 1) r1 = NN - 1;
        cp_async16(&dsm[buf][lrow0][lcol0], &g_dst[(b * NN + r0) * 32 + lcol0]);
        cp_async16(&dsm[buf][lrow1][lcol1], &g_dst[(b * NN + r1) * 32 + lcol1]);
    };

    const int NJT = 32;
    // ---------------- pass 1: row norms ----------------
    prefetch(0, 0); cp_commit();
    float sumsq[4] = {};
    for (int jt = 0; jt < NJT; jt++) {
        int j0 = jt * 64;
        if (jt + 1 < NJT) { prefetch((jt + 1) & 1, j0 + 64); cp_commit(); cp_wait<1>(); }
        else              { cp_wait<0>(); }
        __syncthreads();
        int buf = jt & 1;
#pragma unroll
        for (int half = 0; half < 2; half++) {
            int jj = lane + 32 * half;
            float4 dv[8];
#pragma unroll
            for (int r = 0; r < 8; r++) dv[r] = *(float4*)&dsm[buf][jj][r * 4];
            bool valid = (j0 + jj < NN);
#pragma unroll
            for (int c = 0; c < 4; c++) {
                int qq = w * 4 + c;
                float s = 0.f;
#pragma unroll
                for (int r = 0; r < 8; r++) s += dot4(*(float4*)&ssm[qq][r * 4], dv[r]);
                if (valid) sumsq[c] += s * s;
            }
        }
        __syncthreads();
    }
#pragma unroll
    for (int c = 0; c < 4; c++) {
        float red = sumsq[c];
#pragma unroll
        for (int off = 16; off; off >>= 1) red += __shfl_xor_sync(0xffffffffu, red, off);
        if (lane == 0) normsm[w * 4 + c] = fmaxf(sqrtf(red) * fabsf(scale), 1e-12f);
    }
    __syncthreads();
    // ---------------- pass 2: ballot mask bits ----------------
    prefetch(0, 0); cp_commit();
    for (int jt = 0; jt < NJT; jt++) {
        int j0 = jt * 64;
        if (jt + 1 < NJT) { prefetch((jt + 1) & 1, j0 + 64); cp_commit(); cp_wait<1>(); }
        else              { cp_wait<0>(); }
        __syncthreads();
        int buf = jt & 1;
#pragma unroll
        for (int half = 0; half < 2; half++) {
            int jj = lane + 32 * half;
            float4 dv[8];
#pragma unroll
            for (int r = 0; r < 8; r++) dv[r] = *(float4*)&dsm[buf][jj][r * 4];
#pragma unroll
            for (int c = 0; c < 4; c++) {
                int qq = w * 4 + c;
                int q = q0 + qq;
                float inv = scale / normsm[qq];
                float s = 0.f;
#pragma unroll
                for (int r = 0; r < 8; r++) s += dot4(*(float4*)&ssm[qq][r * 4], dv[r]);
                float val = s * inv + ((j0 + jj) == q ? 1.f : 0.f);
                unsigned word = __ballot_sync(0xffffffffu, val <= 0.f);
                if (lane == 0 && q < NN) g_maskbits[(b * NN + q) * 64 + jt * 2 + half] = word;
            }
        }
        __syncthreads();
    }
}

// ---------------- 9) attention-2: 2 queries/warp, shared K loads, half-warp PV ----------------
__global__ __launch_bounds__(256) void k_attn2() {
    __shared__ float ysm[2][64][68];
    __shared__ float qsm[16][68];
    __shared__ float psm[8][2][64];
    int t = threadIdx.x, w = t >> 5, lane = t & 31;
    int b = blockIdx.y;
    int qA = blockIdx.x * 16 + w * 2;
    int qB = qA + 1;
    const float* yb = g_y + b * (NN * 64);
    const unsigned* mrowA = g_maskbits + (b * NN + qA) * 64;
    const unsigned* mrowB = g_maskbits + (b * NN + qB) * 64;
    // load 16 query rows
    {
        int row = t >> 4, col = (t & 15) << 2;
        *(float4*)&qsm[row][col] = *(const float4*)&yb[(blockIdx.x * 16 + row) * 64 + col];
    }

    int lrow0 = t >> 4, lcol0 = (t & 15) << 2;
    auto prefetch = [&](int buf, int j0) {
#pragma unroll
        for (int r = 0; r < 4; r++) {
            int row = lrow0 + 16 * r;
            int grow = j0 + row; if (grow > NN - 1) grow = NN - 1;
            cp_async16(&ysm[buf][row][lcol0], &yb[grow * 64 + lcol0]);
        }
    };

    const int NT = (NN + 63) / 64;  // 32
    prefetch(0, 0); cp_commit();

    float mxA = -1e30f, mxB = -1e30f;
    float lA = 0.f, lB = 0.f;          // per-lane partials
    float4 acc4[16];
#pragma unroll
    for (int r = 0; r < 16; r++) acc4[r] = make_float4(0.f, 0.f, 0.f, 0.f);
    int hq = lane >> 4, hl = lane & 15;   // half-warp role: 0->qA, 1->qB

    for (int it = 0; it < NT; it++) {
        int j0 = it * 64;
        if (it + 1 < NT) { prefetch((it + 1) & 1, j0 + 64); cp_commit(); cp_wait<1>(); }
        else             { cp_wait<0>(); }
        __syncthreads();
        int buf = it & 1;
        // ---- scores for both queries (keys: lane, lane+32) ----
        float sA0 = 0.f, sA1 = 0.f, sB0 = 0.f, sB1 = 0.f;
#pragma unroll
        for (int r = 0; r < 16; r++) {
            float4 k0 = *(float4*)&ysm[buf][lane][r * 4];
            float4 k1 = *(float4*)&ysm[buf][lane + 32][r * 4];
            float4 qa = *(float4*)&qsm[w * 2][r * 4];
            float4 qb = *(float4*)&qsm[w * 2 + 1][r * 4];
            sA0 += dot4(qa, k0); sA1 += dot4(qa, k1);
            sB0 += dot4(qb, k0); sB1 += dot4(qb, k1);
        }
        unsigned wA0 = mrowA[it * 2], wA1 = mrowA[it * 2 + 1];
        unsigned wB0 = mrowB[it * 2], wB1 = mrowB[it * 2 + 1];
        sA0 = sA0 * 0.125f + (((wA0 >> lane) & 1u) ? -1e9f : 0.f);
        sA1 = sA1 * 0.125f + (((wA1 >> lane) & 1u) ? -1e9f : 0.f);
        sB0 = sB0 * 0.125f + (((wB0 >> lane) & 1u) ? -1e9f : 0.f);
        sB1 = sB1 * 0.125f + (((wB1 >> lane) & 1u) ? -1e9f : 0.f);
        if (j0 + lane >= NN)      { sA0 = -1e30f; sB0 = -1e30f; }
        if (j0 + 32 + lane >= NN) { sA1 = -1e30f; sB1 = -1e30f; }
        float tA = fmaxf(sA0, sA1), tB = fmaxf(sB0, sB1);
#pragma unroll
        for (int off = 16; off; off >>= 1) {
            tA = fmaxf(tA, __shfl_xor_sync(0xffffffffu, tA, off));
            tB = fmaxf(tB, __shfl_xor_sync(0xffffffffu, tB, off));
        }
        bool rsA = (tA > mxA), rsB = (tB > mxB);
        float fA = rsA ? __expf(mxA - tA) : 1.f;
        float fB = rsB ? __expf(mxB - tB) : 1.f;
        if (rsA) { lA *= fA; mxA = tA; }
        if (rsB) { lB *= fB; mxB = tB; }
        if (rsA || rsB) {
            float f = hq ? fB : fA;
#pragma unroll
            for (int r = 0; r < 16; r++) {
                acc4[r].x *= f; acc4[r].y *= f; acc4[r].z *= f; acc4[r].w *= f;
            }
        }
        float pA0 = __expf(sA0 - mxA), pA1 = __expf(sA1 - mxA);
        float pB0 = __expf(sB0 - mxB), pB1 = __expf(sB1 - mxB);
        lA += pA0 + pA1; lB += pB0 + pB1;
        psm[w][0][lane]      = pA0;
        psm[w][0][lane + 32] = pA1;
        psm[w][1][lane]      = pB0;
        psm[w][1][lane + 32] = pB1;
        __syncwarp();
        // ---- PV accumulate: half-warp per query, 4 keys per lane ----
        const float* pp = &psm[w][hq][0];
#pragma unroll
        for (int c = 0; c < 4; c++) {
            int j = hl + 16 * c;
            float p = pp[j];
#pragma unroll
            for (int r = 0; r < 16; r++) {
                float4 v = *(float4*)&ysm[buf][j][r * 4];
                acc4[r].x += p * v.x; acc4[r].y += p * v.y;
                acc4[r].z += p * v.z; acc4[r].w += p * v.w;
            }
        }
        __syncthreads();
    }
    // normalizers (full-warp partial sums)
#pragma unroll
    for (int off = 16; off; off >>= 1) {
        lA += __shfl_xor_sync(0xffffffffu, lA, off);
        lB += __shfl_xor_sync(0xffffffffu, lB, off);
    }
    float inv = 1.f / (hq ? lB : lA);
    // halving butterfly within 16-lane half: lane ends owning dims [4*hl .. 4*hl+3]
#pragma unroll
    for (int r = 0; r < 8; r++) {
        float4 send = (hl & 8) ? acc4[r] : acc4[r + 8];
        float4 oth = shfl_xor_f4(send, 8);
        float4 keep = (hl & 8) ? acc4[r + 8] : acc4[r];
        acc4[r] = make_float4(keep.x + oth.x, keep.y + oth.y, keep.z + oth.z, keep.w + oth.w);
    }
#pragma unroll
    for (int r = 0; r < 4; r++) {
        float4 send = (hl & 4) ? acc4[r] : acc4[r + 4];
        float4 oth = shfl_xor_f4(send, 4);
        float4 keep = (hl & 4) ? acc4[r + 4] : acc4[r];
        acc4[r] = make_float4(keep.x + oth.x, keep.y + oth.y, keep.z + oth.z, keep.w + oth.w);
    }
#pragma unroll
    for (int r = 0; r < 2; r++) {
        float4 send = (hl & 2) ? acc4[r] : acc4[r + 2];
        float4 oth = shfl_xor_f4(send, 2);
        float4 keep = (hl & 2) ? acc4[r + 2] : acc4[r];
        acc4[r] = make_float4(keep.x + oth.x, keep.y + oth.y, keep.z + oth.z, keep.w + oth.w);
    }
    {
        float4 send = (hl & 1) ? acc4[0] : acc4[1];
        float4 oth = shfl_xor_f4(send, 1);
        float4 keep = (hl & 1) ? acc4[1] : acc4[0];
        acc4[0] = make_float4((keep.x + oth.x) * inv, (keep.y + oth.y) * inv,
                              (keep.z + oth.z) * inv, (keep.w + oth.w) * inv);
    }
    int q = hq ? qB : qA;
    *(float4*)&g_y2[(b * NN + q) * 64 + 4 * hl] = acc4[0];
}

// ---------------- 10) residual + LN(lnA) + horizon predictor ----------------
__global__ __launch_bounds__(256) void k_final(const float* __restrict__ lg,
                                               const float* __restrict__ lb,
                                               const float* __restrict__ pw,
                                               const float* __restrict__ pb,
                                               float* __restrict__ out) {
    __shared__ float rsm[8][64];
    __shared__ float pwsm[64 * 24];
    int t = threadIdx.x, w = t >> 5, lane = t & 31;
    int m = blockIdx.x * 8 + w;
    for (int idx = t; idx < 24 * 64; idx += 256) {
        int o = idx >> 6, d = idx & 63;
        pwsm[d * 24 + o] = pw[idx];
    }
    float v0 = g_y2[m * 64 + lane]      + g_node[m * 64 + lane];
    float v1 = g_y2[m * 64 + 32 + lane] + g_node[m * 64 + 32 + lane];
    float s = v0 + v1;
#pragma unroll
    for (int off = 16; off; off >>= 1) s += __shfl_xor_sync(0xffffffffu, s, off);
    float mean = s * (1.f / 64.f);
    float d0 = v0 - mean, d1 = v1 - mean;
    float vs = d0 * d0 + d1 * d1;
#pragma unroll
    for (int off = 16; off; off >>= 1) vs += __shfl_xor_sync(0xffffffffu, vs, off);
    float rs = rsqrtf(vs * (1.f / 64.f) + 1e-5f);
    rsm[w][lane]      = d0 * rs * lg[lane]      + lb[lane];
    rsm[w][lane + 32] = d1 * rs * lg[lane + 32] + lb[lane + 32];
    __syncthreads();
    if (lane < 24) {
        float acc = pb[lane];
#pragma unroll
        for (int d = 0; d < 64; d++) acc += rsm[w][d] * pwsm[d * 24 + lane];
        out[m * 24 + lane] = acc;
    }
}

// ---------------- launch ----------------
extern "C" void kernel_launch(void* const* d_in, const int* in_sizes, int n_in,
                              void* d_out, int out_size) {
    const float* x        = (const float*)d_in[0];
    const float* conv_w   = (const float*)d_in[1];
    const float* conv_b   = (const float*)d_in[2];
    const float* bn_g     = (const float*)d_in[3];
    const float* bn_b     = (const float*)d_in[4];
    const float* proj_w   = (const float*)d_in[5];
    const float* proj_b   = (const float*)d_in[6];
    const float* ln1_g    = (const float*)d_in[7];
    const float* ln1_b    = (const float*)d_in[8];
    const float* src_w    = (const float*)d_in[9];
    const float* src_b    = (const float*)d_in[10];
    const float* dst_w    = (const float*)d_in[11];
    const float* dst_b    = (const float*)d_in[12];
    const float* edge_sc  = (const float*)d_in[13];
    const float* inp_w    = (const float*)d_in[14];
    const float* inp_b    = (const float*)d_in[15];
    const float* out_w    = (const float*)d_in[16];
    const float* out_b    = (const float*)d_in[17];
    const float* lnA_g    = (const float*)d_in[18];
    const float* lnA_b    = (const float*)d_in[19];
    const float* pred_w   = (const float*)d_in[20];
    const float* pred_b   = (const float*)d_in[21];
    float* out = (float*)d_out;

    k_conv<<<dim3((BN + 255) / 256, TT), 256>>>(x, conv_w, conv_b, bn_g, bn_b);
    k_transw<<<(FT * HH + 255) / 256, 256>>>(proj_w);
    k_proj<<<BN / 64, 256>>>(proj_b);
    k_ln1<<<BN / 8, 256>>>(ln1_g, ln1_b);
    k_sdq<<<BN / 64, 256>>>(src_w, src_b, dst_w, dst_b, inp_w, inp_b);
    k_attn1<<<dim3(NN / 16, NHEADS, BB), 256>>>();
    k_outp<<<BN / 64, 256>>>(out_w, out_b);
    k_mask<<<dim3((NN + 31) / 32, BB), 256>>>(edge_sc);
    k_attn2<<<dim3(NN / 16, BB), 256>>>();
    k_final<<<BN / 8, 256>>>(lnA_g, lnA_b, pred_w, pred_b, out);
}

// round 5
// speedup vs baseline: 2.0167x; 1.1015x over previous
#include <cuda_runtime.h>
#include <math.h>

#define BB 4
#define TT 48
#define NN 2000
#define BN (BB*NN)      // 8000
#define FF 16
#define HH 64
#define NHEADS 4
#define HD 16
#define HOR 24
#define PP 32
#define FT (FF*TT)      // 768

typedef unsigned long long u64;

// ---------------- scratch (device globals: no allocation) ----------------
__device__ float g_hT[FT*BN];      // conv features, k-major [768][8000]
__device__ float g_projT[FT*HH];   // proj_w transposed [768][64]
__device__ float g_z[BN*HH];
__device__ float g_node[BN*HH];
__device__ float g_src[BN*PP];
__device__ float g_dst[BN*PP];
__device__ float g_qkv[BN*3*HH];
__device__ float g_yattn[BN*HH];
__device__ float g_y[BN*HH];
__device__ float g_y2[BN*HH];
__device__ unsigned g_maskbits[BB*NN*64];   // 64 words per row

__device__ __forceinline__ float dot4(float4 a, float4 b) {
    return a.x*b.x + a.y*b.y + a.z*b.z + a.w*b.w;
}
// ---- packed fp32x2 (FFMA2) helpers: exact fp32 semantics, 2 MACs/inst ----
__device__ __forceinline__ void fma2(u64& d, u64 a, u64 b) {
    asm("fma.rn.f32x2 %0, %1, %2, %0;" : "+l"(d) : "l"(a), "l"(b));
}
__device__ __forceinline__ void mul2(u64& d, u64 b) {
    asm("mul.rn.f32x2 %0, %0, %1;" : "+l"(d) : "l"(b));
}
__device__ __forceinline__ void add2(u64& d, u64 b) {
    asm("add.rn.f32x2 %0, %0, %1;" : "+l"(d) : "l"(b));
}
__device__ __forceinline__ u64 pack2(float p) {
    u64 r; asm("mov.b64 %0, {%1, %1};" : "=l"(r) : "f"(p)); return r;
}
__device__ __forceinline__ float hadd2(u64 v) {
    float lo, hi; asm("mov.b64 {%0, %1}, %2;" : "=f"(lo), "=f"(hi) : "l"(v));
    return lo + hi;
}
__device__ __forceinline__ void cp_async16(void* smem, const void* gmem) {
    unsigned s = (unsigned)__cvta_generic_to_shared(smem);
    asm volatile("cp.async.cg.shared.global [%0], [%1], 16;\n" :: "r"(s), "l"(gmem));
}
__device__ __forceinline__ void cp_commit() { asm volatile("cp.async.commit_group;\n"); }
template<int N> __device__ __forceinline__ void cp_wait() {
    asm volatile("cp.async.wait_group %0;\n" :: "n"(N));
}

// ---------------- 1) conv1d(SAME,K=3) + BN(eval) + ReLU -> g_hT ----------------
__global__ __launch_bounds__(256) void k_conv(const float* __restrict__ x,
                                              const float* __restrict__ cw,
                                              const float* __restrict__ cb,
                                              const float* __restrict__ bng,
                                              const float* __restrict__ bnb) {
    int node = blockIdx.x * 256 + threadIdx.x;
    int t = blockIdx.y;
    if (node >= BN) return;
    int b = node / NN, n = node - b * NN;
    const float* xb = x + b * (TT * NN) + n;
    float xm1 = (t > 0)      ? xb[(t - 1) * NN] : 0.f;
    float x0  =                xb[t * NN];
    float xp1 = (t < TT - 1) ? xb[(t + 1) * NN] : 0.f;
    float bns = rsqrtf(1.0f + 1e-5f);
#pragma unroll
    for (int f = 0; f < FF; f++) {
        float v = cw[f*3]*xm1 + cw[f*3+1]*x0 + cw[f*3+2]*xp1 + cb[f];
        v = v * (bng[f] * bns) + bnb[f];
        g_hT[(f * TT + t) * BN + node] = fmaxf(v, 0.f);
    }
}

// ---------------- 2) transpose proj_w [64][768] -> [768][64] ----------------
__global__ __launch_bounds__(256) void k_transw(const float* __restrict__ w) {
    int idx = blockIdx.x * 256 + threadIdx.x;
    if (idx < FT * HH) {
        int k = idx >> 6, h = idx & 63;
        g_projT[idx] = w[h * FT + k];
    }
}

// ---------------- 3) z = flat @ proj_w^T + b (tiled SGEMM, double-buffered, FFMA2) ----------------
__global__ __launch_bounds__(256) void k_proj(const float* __restrict__ pb) {
    __shared__ float Asm[2][32][64];
    __shared__ float Bsm[2][32][64];
    int t = threadIdx.x;
    int m0 = blockIdx.x * 64;
    int tx = t & 15, ty = t >> 4;
    int lrow0 = t >> 4, lcol0 = (t & 15) << 2;
    int lrow1 = (t + 256) >> 4, lcol1 = ((t + 256) & 15) << 2;
    u64 c2[4][2] = {};

    const int NT = FT / 32;  // 24
    cp_async16(&Asm[0][lrow0][lcol0], &g_hT[lrow0 * BN + m0 + lcol0]);
    cp_async16(&Asm[0][lrow1][lcol1], &g_hT[lrow1 * BN + m0 + lcol1]);
    cp_async16(&Bsm[0][lrow0][lcol0], &g_projT[lrow0 * HH + lcol0]);
    cp_async16(&Bsm[0][lrow1][lcol1], &g_projT[lrow1 * HH + lcol1]);
    cp_commit();

    for (int it = 0; it < NT; it++) {
        if (it + 1 < NT) {
            int k0 = (it + 1) * 32, nb = (it + 1) & 1;
            cp_async16(&Asm[nb][lrow0][lcol0], &g_hT[(k0 + lrow0) * BN + m0 + lcol0]);
            cp_async16(&Asm[nb][lrow1][lcol1], &g_hT[(k0 + lrow1) * BN + m0 + lcol1]);
            cp_async16(&Bsm[nb][lrow0][lcol0], &g_projT[(k0 + lrow0) * HH + lcol0]);
            cp_async16(&Bsm[nb][lrow1][lcol1], &g_projT[(k0 + lrow1) * HH + lcol1]);
            cp_commit();
            cp_wait<1>();
        } else {
            cp_wait<0>();
        }
        __syncthreads();
        int buf = it & 1;
#pragma unroll
        for (int kk = 0; kk < 32; kk++) {
            float4 a = *(float4*)&Asm[buf][kk][ty * 4];
            ulonglong2 bv = *(ulonglong2*)&Bsm[buf][kk][tx * 4];
            float av[4] = {a.x, a.y, a.z, a.w};
#pragma unroll
            for (int i = 0; i < 4; i++) {
                u64 a2 = pack2(av[i]);
                fma2(c2[i][0], a2, bv.x);
                fma2(c2[i][1], a2, bv.y);
            }
        }
        __syncthreads();
    }
    u64 pb0 = *(const u64*)&pb[tx * 4];
    u64 pb1 = *(const u64*)&pb[tx * 4 + 2];
#pragma unroll
    for (int i = 0; i < 4; i++) {
        add2(c2[i][0], pb0);
        add2(c2[i][1], pb1);
        ulonglong2 o; o.x = c2[i][0]; o.y = c2[i][1];
        *(ulonglong2*)&g_z[(m0 + ty * 4 + i) * HH + tx * 4] = o;
    }
}

// ---------------- 4) LayerNorm + ReLU -> g_node ----------------
__global__ __launch_bounds__(256) void k_ln1(const float* __restrict__ g,
                                             const float* __restrict__ bb) {
    int w = threadIdx.x >> 5, lane = threadIdx.x & 31;
    int m = blockIdx.x * 8 + w;
    float v0 = g_z[m * 64 + lane], v1 = g_z[m * 64 + 32 + lane];
    float s = v0 + v1;
#pragma unroll
    for (int off = 16; off; off >>= 1) s += __shfl_xor_sync(0xffffffffu, s, off);
    float mean = s * (1.f / 64.f);
    float d0 = v0 - mean, d1 = v1 - mean;
    float vs = d0 * d0 + d1 * d1;
#pragma unroll
    for (int off = 16; off; off >>= 1) vs += __shfl_xor_sync(0xffffffffu, vs, off);
    float rs = rsqrtf(vs * (1.f / 64.f) + 1e-5f);
    g_node[m * 64 + lane]      = fmaxf(d0 * rs * g[lane]      + bb[lane],      0.f);
    g_node[m * 64 + 32 + lane] = fmaxf(d1 * rs * g[lane + 32] + bb[lane + 32], 0.f);
}

// ---------------- 5) src/dst (leaky 0.2) + qkv, fused (FFMA2) ----------------
__global__ __launch_bounds__(256) void k_sdq(const float* __restrict__ sw, const float* __restrict__ sb,
                                             const float* __restrict__ dw, const float* __restrict__ db,
                                             const float* __restrict__ iw, const float* __restrict__ ib) {
    __shared__ float nsm[64 * 64];
    int t = threadIdx.x;
    int m0 = blockIdx.x * 64;
#pragma unroll
    for (int r = 0; r < 4; r++) {
        int idx = (t + 256 * r) * 4;
        *(float4*)&nsm[idx] = *(const float4*)&g_node[m0 * 64 + idx];
    }
    __syncthreads();
    const float* wrow; float bias;
    if (t < 32)       { wrow = sw + t * 64;        bias = sb[t]; }
    else if (t < 64)  { wrow = dw + (t - 32) * 64; bias = db[t - 32]; }
    else              { wrow = iw + (t - 64) * 64; bias = ib[t - 64]; }
    u64 wr[32];
#pragma unroll
    for (int r = 0; r < 16; r++) {
        ulonglong2 v = *(const ulonglong2*)&wrow[r * 4];
        wr[2*r] = v.x; wr[2*r+1] = v.y;
    }
    for (int m = 0; m < 64; m++) {
        u64 a = 0;
#pragma unroll
        for (int r = 0; r < 16; r++) {
            ulonglong2 nv = *(ulonglong2*)&nsm[m * 64 + r * 4];
            fma2(a, wr[2*r], nv.x);
            fma2(a, wr[2*r+1], nv.y);
        }
        float acc = hadd2(a) + bias;
        int gm = m0 + m;
        if (t < 64) {
            acc = (acc > 0.f) ? acc : 0.2f * acc;
            if (t < 32) g_src[gm * 32 + t] = acc;
            else        g_dst[gm * 32 + t - 32] = acc;
        } else {
            g_qkv[gm * 192 + t - 64] = acc;
        }
    }
}

// ---------------- 6) attention-1: 4 queries/warp, 128 threads, FFMA2 ----------------
__global__ __launch_bounds__(128) void k_attn1() {
    __shared__ float Ksm[2][128][20];
    __shared__ float Vsm[2][128][20];
    int t = threadIdx.x, w = t >> 5, lane = t & 31;
    int b = blockIdx.z, h = blockIdx.y;
    int q0 = blockIdx.x * 16 + w * 4;   // queries q0..q0+3
    const float* qkv_b = g_qkv + b * (NN * 192);
    u64 qp[4][8];
#pragma unroll
    for (int qq = 0; qq < 4; qq++) {
        const float* qptr = qkv_b + (q0 + qq) * 192 + h * 16;
#pragma unroll
        for (int r = 0; r < 4; r++) {
            ulonglong2 v = *(const ulonglong2*)&qptr[r * 4];
            qp[qq][2*r] = v.x; qp[qq][2*r+1] = v.y;
        }
    }
    const int NT = (NN + 127) / 128;  // 16

    auto prefetch = [&](int buf, int j0) {
        int row = j0 + t;
        if (row > NN - 1) row = NN - 1;
        const float* kp = qkv_b + row * 192 + 64 + h * 16;
        cp_async16(&Ksm[buf][t][0],  kp);
        cp_async16(&Ksm[buf][t][4],  kp + 4);
        cp_async16(&Ksm[buf][t][8],  kp + 8);
        cp_async16(&Ksm[buf][t][12], kp + 12);
        const float* vp = kp + 64;
        cp_async16(&Vsm[buf][t][0],  vp);
        cp_async16(&Vsm[buf][t][4],  vp + 4);
        cp_async16(&Vsm[buf][t][8],  vp + 8);
        cp_async16(&Vsm[buf][t][12], vp + 12);
    };

    prefetch(0, 0); cp_commit();

    float mx[4] = {-1e30f, -1e30f, -1e30f, -1e30f};
    float l[4] = {};
    u64 acc[4][8] = {};
    for (int it = 0; it < NT; it++) {
        int j0 = it * 128;
        if (it + 1 < NT) { prefetch((it + 1) & 1, j0 + 128); cp_commit(); cp_wait<1>(); }
        else             { cp_wait<0>(); }
        __syncthreads();
        int buf = it & 1;
        float s[4][4];
#pragma unroll
        for (int c = 0; c < 4; c++) {
            int jj = lane + 32 * c;
            ulonglong2 ka = *(ulonglong2*)&Ksm[buf][jj][0];
            ulonglong2 kb = *(ulonglong2*)&Ksm[buf][jj][4];
            ulonglong2 kc = *(ulonglong2*)&Ksm[buf][jj][8];
            ulonglong2 kd = *(ulonglong2*)&Ksm[buf][jj][12];
            u64 k[8] = {ka.x, ka.y, kb.x, kb.y, kc.x, kc.y, kd.x, kd.y};
            bool oob = (j0 + jj >= NN);
#pragma unroll
            for (int qq = 0; qq < 4; qq++) {
                u64 d2 = 0;
#pragma unroll
                for (int r = 0; r < 8; r++) fma2(d2, qp[qq][r], k[r]);
                s[qq][c] = oob ? -1e30f : 0.25f * hadd2(d2);
            }
        }
        float t4[4];
#pragma unroll
        for (int qq = 0; qq < 4; qq++)
            t4[qq] = fmaxf(fmaxf(s[qq][0], s[qq][1]), fmaxf(s[qq][2], s[qq][3]));
#pragma unroll
        for (int off = 16; off; off >>= 1) {
#pragma unroll
            for (int qq = 0; qq < 4; qq++)
                t4[qq] = fmaxf(t4[qq], __shfl_xor_sync(0xffffffffu, t4[qq], off));
        }
#pragma unroll
        for (int qq = 0; qq < 4; qq++) {
            if (t4[qq] > mx[qq]) {
                float f = __expf(mx[qq] - t4[qq]);
                l[qq] *= f;
                u64 f2 = pack2(f);
#pragma unroll
                for (int r = 0; r < 8; r++) mul2(acc[qq][r], f2);
                mx[qq] = t4[qq];
            }
        }
#pragma unroll
        for (int c = 0; c < 4; c++) {
            int jj = lane + 32 * c;
            ulonglong2 va = *(ulonglong2*)&Vsm[buf][jj][0];
            ulonglong2 vb = *(ulonglong2*)&Vsm[buf][jj][4];
            ulonglong2 vc = *(ulonglong2*)&Vsm[buf][jj][8];
            ulonglong2 vd = *(ulonglong2*)&Vsm[buf][jj][12];
            u64 v[8] = {va.x, va.y, vb.x, vb.y, vc.x, vc.y, vd.x, vd.y};
#pragma unroll
            for (int qq = 0; qq < 4; qq++) {
                float p = __expf(s[qq][c] - mx[qq]);
                l[qq] += p;
                u64 p2 = pack2(p);
#pragma unroll
                for (int r = 0; r < 8; r++) fma2(acc[qq][r], p2, v[r]);
            }
        }
        __syncthreads();
    }
#pragma unroll
    for (int off = 16; off; off >>= 1) {
#pragma unroll
        for (int qq = 0; qq < 4; qq++) {
            l[qq] += __shfl_xor_sync(0xffffffffu, l[qq], off);
#pragma unroll
            for (int r = 0; r < 8; r++) {
                u64 o = __shfl_xor_sync(0xffffffffu, acc[qq][r], off);
                add2(acc[qq][r], o);
            }
        }
    }
    if (lane == 0) {
#pragma unroll
        for (int qq = 0; qq < 4; qq++) {
            u64 i2 = pack2(1.f / l[qq]);
#pragma unroll
            for (int r = 0; r < 8; r++) mul2(acc[qq][r], i2);
            float* op = g_yattn + (b * NN + q0 + qq) * 64 + h * 16;
#pragma unroll
            for (int r = 0; r < 4; r++) {
                ulonglong2 o; o.x = acc[qq][2*r]; o.y = acc[qq][2*r+1];
                *(ulonglong2*)&op[r * 4] = o;
            }
        }
    }
}

// ---------------- 7) out projection y = y_attn @ out_w^T + out_b (FFMA2) ----------------
__global__ __launch_bounds__(256) void k_outp(const float* __restrict__ ow,
                                              const float* __restrict__ ob) {
    __shared__ float ysm[64 * 64];
    int t = threadIdx.x;
    int m0 = blockIdx.x * 64;
#pragma unroll
    for (int r = 0; r < 4; r++) {
        int idx = (t + 256 * r) * 4;
        *(float4*)&ysm[idx] = *(const float4*)&g_yattn[m0 * 64 + idx];
    }
    __syncthreads();
    int o = t & 63, gq = t >> 6;
    u64 wr[32];
#pragma unroll
    for (int r = 0; r < 16; r++) {
        ulonglong2 v = *(const ulonglong2*)&ow[o * 64 + r * 4];
        wr[2*r] = v.x; wr[2*r+1] = v.y;
    }
    float bias = ob[o];
    for (int rr = 0; rr < 16; rr++) {
        int mm = gq * 16 + rr;
        u64 a = 0;
#pragma unroll
        for (int r = 0; r < 16; r++) {
            ulonglong2 nv = *(ulonglong2*)&ysm[mm * 64 + r * 4];
            fma2(a, wr[2*r], nv.x);
            fma2(a, wr[2*r+1], nv.y);
        }
        g_y[(m0 + mm) * 64 + o] = hadd2(a) + bias;
    }
}

// ---------------- 8) adjacency mask bits (norm pass + ballot pass, FFMA2) ----------------
__global__ __launch_bounds__(256) void k_mask(const float* __restrict__ es) {
    __shared__ float ssm[32][36];
    __shared__ float dsm[2][64][36];
    __shared__ float normsm[32];
    int t = threadIdx.x, w = t >> 5, lane = t & 31;
    int b = blockIdx.y;
    int q0 = blockIdx.x * 32;
    float scale = es[0];
    {
        int row = t >> 3, col = (t & 7) << 2;
        int q = q0 + row;
        float4 v = make_float4(0.f, 0.f, 0.f, 0.f);
        if (q < NN) v = *(const float4*)&g_src[(b * NN + q) * 32 + col];
        *(float4*)&ssm[row][col] = v;
    }
    int lrow0 = t >> 3, lcol0 = (t & 7) << 2;
    int lrow1 = (t + 256) >> 3, lcol1 = ((t + 256) & 7) << 2;
    auto prefetch = [&](int buf, int j0) {
        int r0 = j0 + lrow0; if (r0 > NN - 1) r0 = NN - 1;
        int r1 = j0 + lrow1; if (r1 > NN - 1) r1 = NN - 1;
        cp_async16(&dsm[buf][lrow0][lcol0], &g_dst[(b * NN + r0) * 32 + lcol0]);
        cp_async16(&dsm[buf][lrow1][lcol1], &g_dst[(b * NN + r1) * 32 + lcol1]);
    };
    __syncthreads();
    // hoist this warp's 4 query rows into registers (used by both passes)
    u64 qu[4][16];
#pragma unroll
    for (int c = 0; c < 4; c++) {
#pragma unroll
        for (int r = 0; r < 8; r++) {
            ulonglong2 v = *(ulonglong2*)&ssm[w * 4 + c][r * 4];
            qu[c][2*r] = v.x; qu[c][2*r+1] = v.y;
        }
    }

    const int NJT = 32;
    // ---------------- pass 1: row norms ----------------
    prefetch(0, 0); cp_commit();
    float sumsq[4] = {};
    for (int jt = 0; jt < NJT; jt++) {
        int j0 = jt * 64;
        if (jt + 1 < NJT) { prefetch((jt + 1) & 1, j0 + 64); cp_commit(); cp_wait<1>(); }
        else              { cp_wait<0>(); }
        __syncthreads();
        int buf = jt & 1;
#pragma unroll
        for (int half = 0; half < 2; half++) {
            int jj = lane + 32 * half;
            u64 dv[16];
#pragma unroll
            for (int r = 0; r < 8; r++) {
                ulonglong2 v = *(ulonglong2*)&dsm[buf][jj][r * 4];
                dv[2*r] = v.x; dv[2*r+1] = v.y;
            }
            bool valid = (j0 + jj < NN);
#pragma unroll
            for (int c = 0; c < 4; c++) {
                u64 a = 0;
#pragma unroll
                for (int r = 0; r < 16; r++) fma2(a, qu[c][r], dv[r]);
                float s = hadd2(a);
                if (valid) sumsq[c] += s * s;
            }
        }
        __syncthreads();
    }
#pragma unroll
    for (int c = 0; c < 4; c++) {
        float red = sumsq[c];
#pragma unroll
        for (int off = 16; off; off >>= 1) red += __shfl_xor_sync(0xffffffffu, red, off);
        if (lane == 0) normsm[w * 4 + c] = fmaxf(sqrtf(red) * fabsf(scale), 1e-12f);
    }
    __syncthreads();
    // ---------------- pass 2: ballot mask bits ----------------
    prefetch(0, 0); cp_commit();
    for (int jt = 0; jt < NJT; jt++) {
        int j0 = jt * 64;
        if (jt + 1 < NJT) { prefetch((jt + 1) & 1, j0 + 64); cp_commit(); cp_wait<1>(); }
        else              { cp_wait<0>(); }
        __syncthreads();
        int buf = jt & 1;
#pragma unroll
        for (int half = 0; half < 2; half++) {
            int jj = lane + 32 * half;
            u64 dv[16];
#pragma unroll
            for (int r = 0; r < 8; r++) {
                ulonglong2 v = *(ulonglong2*)&dsm[buf][jj][r * 4];
                dv[2*r] = v.x; dv[2*r+1] = v.y;
            }
#pragma unroll
            for (int c = 0; c < 4; c++) {
                int qq = w * 4 + c;
                int q = q0 + qq;
                float inv = scale / normsm[qq];
                u64 a = 0;
#pragma unroll
                for (int r = 0; r < 16; r++) fma2(a, qu[c][r], dv[r]);
                float val = hadd2(a) * inv + ((j0 + jj) == q ? 1.f : 0.f);
                unsigned word = __ballot_sync(0xffffffffu, val <= 0.f);
                if (lane == 0 && q < NN) g_maskbits[(b * NN + q) * 64 + jt * 2 + half] = word;
            }
        }
        __syncthreads();
    }
}

// ---------------- 9) attention-2: 2 queries/warp, half-warp PV, FFMA2 ----------------
__global__ __launch_bounds__(256) void k_attn2() {
    __shared__ float ysm[2][64][68];
    __shared__ float qsm[16][68];
    __shared__ float psm[8][2][64];
    int t = threadIdx.x, w = t >> 5, lane = t & 31;
    int b = blockIdx.y;
    int qA = blockIdx.x * 16 + w * 2;
    int qB = qA + 1;
    const float* yb = g_y + b * (NN * 64);
    const unsigned* mrowA = g_maskbits + (b * NN + qA) * 64;
    const unsigned* mrowB = g_maskbits + (b * NN + qB) * 64;
    {
        int row = t >> 4, col = (t & 15) << 2;
        *(float4*)&qsm[row][col] = *(const float4*)&yb[(blockIdx.x * 16 + row) * 64 + col];
    }

    int lrow0 = t >> 4, lcol0 = (t & 15) << 2;
    auto prefetch = [&](int buf, int j0) {
#pragma unroll
        for (int r = 0; r < 4; r++) {
            int row = lrow0 + 16 * r;
            int grow = j0 + row; if (grow > NN - 1) grow = NN - 1;
            cp_async16(&ysm[buf][row][lcol0], &yb[grow * 64 + lcol0]);
        }
    };

    const int NT = (NN + 63) / 64;  // 32
    prefetch(0, 0); cp_commit();

    float mxA = -1e30f, mxB = -1e30f;
    float lA = 0.f, lB = 0.f;
    u64 accP[32] = {};
    int hq = lane >> 4, hl = lane & 15;

    for (int it = 0; it < NT; it++) {
        int j0 = it * 64;
        if (it + 1 < NT) { prefetch((it + 1) & 1, j0 + 64); cp_commit(); cp_wait<1>(); }
        else             { cp_wait<0>(); }
        __syncthreads();
        int buf = it & 1;
        // ---- scores (packed) ----
        u64 A0 = 0, A1 = 0, B0 = 0, B1 = 0;
#pragma unroll
        for (int r = 0; r < 16; r++) {
            ulonglong2 k0 = *(ulonglong2*)&ysm[buf][lane][r * 4];
            ulonglong2 k1 = *(ulonglong2*)&ysm[buf][lane + 32][r * 4];
            ulonglong2 qa = *(ulonglong2*)&qsm[w * 2][r * 4];
            ulonglong2 qb = *(ulonglong2*)&qsm[w * 2 + 1][r * 4];
            fma2(A0, qa.x, k0.x); fma2(A0, qa.y, k0.y);
            fma2(A1, qa.x, k1.x); fma2(A1, qa.y, k1.y);
            fma2(B0, qb.x, k0.x); fma2(B0, qb.y, k0.y);
            fma2(B1, qb.x, k1.x); fma2(B1, qb.y, k1.y);
        }
        float sA0 = hadd2(A0), sA1 = hadd2(A1), sB0 = hadd2(B0), sB1 = hadd2(B1);
        unsigned wA0 = mrowA[it * 2], wA1 = mrowA[it * 2 + 1];
        unsigned wB0 = mrowB[it * 2], wB1 = mrowB[it * 2 + 1];
        sA0 = sA0 * 0.125f + (((wA0 >> lane) & 1u) ? -1e9f : 0.f);
        sA1 = sA1 * 0.125f + (((wA1 >> lane) & 1u) ? -1e9f : 0.f);
        sB0 = sB0 * 0.125f + (((wB0 >> lane) & 1u) ? -1e9f : 0.f);
        sB1 = sB1 * 0.125f + (((wB1 >> lane) & 1u) ? -1e9f : 0.f);
        if (j0 + lane >= NN)      { sA0 = -1e30f; sB0 = -1e30f; }
        if (j0 + 32 + lane >= NN) { sA1 = -1e30f; sB1 = -1e30f; }
        float tA = fmaxf(sA0, sA1), tB = fmaxf(sB0, sB1);
#pragma unroll
        for (int off = 16; off; off >>= 1) {
            tA = fmaxf(tA, __shfl_xor_sync(0xffffffffu, tA, off));
            tB = fmaxf(tB, __shfl_xor_sync(0xffffffffu, tB, off));
        }
        bool rsA = (tA > mxA), rsB = (tB > mxB);
        float fA = rsA ? __expf(mxA - tA) : 1.f;
        float fB = rsB ? __expf(mxB - tB) : 1.f;
        if (rsA) { lA *= fA; mxA = tA; }
        if (rsB) { lB *= fB; mxB = tB; }
        if (rsA || rsB) {
            u64 f2 = pack2(hq ? fB : fA);
#pragma unroll
            for (int r = 0; r < 32; r++) mul2(accP[r], f2);
        }
        float pA0 = __expf(sA0 - mxA), pA1 = __expf(sA1 - mxA);
        float pB0 = __expf(sB0 - mxB), pB1 = __expf(sB1 - mxB);
        lA += pA0 + pA1; lB += pB0 + pB1;
        psm[w][0][lane]      = pA0;
        psm[w][0][lane + 32] = pA1;
        psm[w][1][lane]      = pB0;
        psm[w][1][lane + 32] = pB1;
        __syncwarp();
        // ---- PV: half-warp per query, 4 keys per lane (packed) ----
        const float* pp = &psm[w][hq][0];
#pragma unroll
        for (int c = 0; c < 4; c++) {
            int j = hl + 16 * c;
            u64 p2 = pack2(pp[j]);
#pragma unroll
            for (int r = 0; r < 16; r++) {
                ulonglong2 v = *(ulonglong2*)&ysm[buf][j][r * 4];
                fma2(accP[2*r],   p2, v.x);
                fma2(accP[2*r+1], p2, v.y);
            }
        }
        __syncthreads();
    }
#pragma unroll
    for (int off = 16; off; off >>= 1) {
        lA += __shfl_xor_sync(0xffffffffu, lA, off);
        lB += __shfl_xor_sync(0xffffffffu, lB, off);
    }
    float inv = 1.f / (hq ? lB : lA);
    // halving butterfly within 16-lane half (on packed u64)
#pragma unroll
    for (int r = 0; r < 16; r++) {
        u64 send = (hl & 8) ? accP[r] : accP[r + 16];
        u64 oth = __shfl_xor_sync(0xffffffffu, send, 8);
        u64 keep = (hl & 8) ? accP[r + 16] : accP[r];
        add2(keep, oth); accP[r] = keep;
    }
#pragma unroll
    for (int r = 0; r < 8; r++) {
        u64 send = (hl & 4) ? accP[r] : accP[r + 8];
        u64 oth = __shfl_xor_sync(0xffffffffu, send, 4);
        u64 keep = (hl & 4) ? accP[r + 8] : accP[r];
        add2(keep, oth); accP[r] = keep;
    }
#pragma unroll
    for (int r = 0; r < 4; r++) {
        u64 send = (hl & 2) ? accP[r] : accP[r + 4];
        u64 oth = __shfl_xor_sync(0xffffffffu, send, 2);
        u64 keep = (hl & 2) ? accP[r + 4] : accP[r];
        add2(keep, oth); accP[r] = keep;
    }
#pragma unroll
    for (int r = 0; r < 2; r++) {
        u64 send = (hl & 1) ? accP[r] : accP[r + 2];
        u64 oth = __shfl_xor_sync(0xffffffffu, send, 1);
        u64 keep = (hl & 1) ? accP[r + 2] : accP[r];
        add2(keep, oth); accP[r] = keep;
    }
    u64 i2 = pack2(inv);
    mul2(accP[0], i2); mul2(accP[1], i2);
    int q = hq ? qB : qA;
    ulonglong2 o; o.x = accP[0]; o.y = accP[1];
    *(ulonglong2*)&g_y2[(b * NN + q) * 64 + 4 * hl] = o;
}

// ---------------- 10) residual + LN(lnA) + horizon predictor ----------------
__global__ __launch_bounds__(256) void k_final(const float* __restrict__ lg,
                                               const float* __restrict__ lb,
                                               const float* __restrict__ pw,
                                               const float* __restrict__ pb,
                                               float* __restrict__ out) {
    __shared__ float rsm[8][64];
    __shared__ float pwsm[64 * 24];
    int t = threadIdx.x, w = t >> 5, lane = t & 31;
    int m = blockIdx.x * 8 + w;
    for (int idx = t; idx < 24 * 64; idx += 256) {
        int o = idx >> 6, d = idx & 63;
        pwsm[d * 24 + o] = pw[idx];
    }
    float v0 = g_y2[m * 64 + lane]      + g_node[m * 64 + lane];
    float v1 = g_y2[m * 64 + 32 + lane] + g_node[m * 64 + 32 + lane];
    float s = v0 + v1;
#pragma unroll
    for (int off = 16; off; off >>= 1) s += __shfl_xor_sync(0xffffffffu, s, off);
    float mean = s * (1.f / 64.f);
    float d0 = v0 - mean, d1 = v1 - mean;
    float vs = d0 * d0 + d1 * d1;
#pragma unroll
    for (int off = 16; off; off >>= 1) vs += __shfl_xor_sync(0xffffffffu, vs, off);
    float rs = rsqrtf(vs * (1.f / 64.f) + 1e-5f);
    rsm[w][lane]      = d0 * rs * lg[lane]      + lb[lane];
    rsm[w][lane + 32] = d1 * rs * lg[lane + 32] + lb[lane + 32];
    __syncthreads();
    if (lane < 24) {
        float acc = pb[lane];
#pragma unroll
        for (int d = 0; d < 64; d++) acc += rsm[w][d] * pwsm[d * 24 + lane];
        out[m * 24 + lane] = acc;
    }
}

// ---------------- launch ----------------
extern "C" void kernel_launch(void* const* d_in, const int* in_sizes, int n_in,
                              void* d_out, int out_size) {
    const float* x        = (const float*)d_in[0];
    const float* conv_w   = (const float*)d_in[1];
    const float* conv_b   = (const float*)d_in[2];
    const float* bn_g     = (const float*)d_in[3];
    const float* bn_b     = (const float*)d_in[4];
    const float* proj_w   = (const float*)d_in[5];
    const float* proj_b   = (const float*)d_in[6];
    const float* ln1_g    = (const float*)d_in[7];
    const float* ln1_b    = (const float*)d_in[8];
    const float* src_w    = (const float*)d_in[9];
    const float* src_b    = (const float*)d_in[10];
    const float* dst_w    = (const float*)d_in[11];
    const float* dst_b    = (const float*)d_in[12];
    const float* edge_sc  = (const float*)d_in[13];
    const float* inp_w    = (const float*)d_in[14];
    const float* inp_b    = (const float*)d_in[15];
    const float* out_w    = (const float*)d_in[16];
    const float* out_b    = (const float*)d_in[17];
    const float* lnA_g    = (const float*)d_in[18];
    const float* lnA_b    = (const float*)d_in[19];
    const float* pred_w   = (const float*)d_in[20];
    const float* pred_b   = (const float*)d_in[21];
    float* out = (float*)d_out;

    k_conv<<<dim3((BN + 255) / 256, TT), 256>>>(x, conv_w, conv_b, bn_g, bn_b);
    k_transw<<<(FT * HH + 255) / 256, 256>>>(proj_w);
    k_proj<<<BN / 64, 256>>>(proj_b);
    k_ln1<<<BN / 8, 256>>>(ln1_g, ln1_b);
    k_sdq<<<BN / 64, 256>>>(src_w, src_b, dst_w, dst_b, inp_w, inp_b);
    k_attn1<<<dim3(NN / 16, NHEADS, BB), 128>>>();
    k_outp<<<BN / 64, 256>>>(out_w, out_b);
    k_mask<<<dim3((NN + 31) / 32, BB), 256>>>(edge_sc);
    k_attn2<<<dim3(NN / 16, BB), 256>>>();
    k_final<<<BN / 8, 256>>>(lnA_g, lnA_b, pred_w, pred_b, out);
}

// round 6
// speedup vs baseline: 2.1651x; 1.0736x over previous
#include <cuda_runtime.h>
#include <math.h>

#define BB 4
#define TT 48
#define NN 2000
#define BN (BB*NN)      // 8000
#define FF 16
#define HH 64
#define NHEADS 4
#define HD 16
#define HOR 24
#define PP 32
#define FT (FF*TT)      // 768

typedef unsigned long long u64;

// ---------------- scratch (device globals: no allocation) ----------------
__device__ float g_hT[FT*BN];      // conv features, k-major [768][8000]
__device__ float g_projT[FT*HH];   // proj_w transposed [768][64]
__device__ float g_z[BN*HH];
__device__ float g_node[BN*HH];
__device__ float g_src[BN*PP];
__device__ float g_dst[BN*PP];
__device__ float g_qkv[BN*3*HH];
__device__ float g_yattn[BN*HH];
__device__ float g_y[BN*HH];
__device__ float g_y2[BN*HH];
__device__ unsigned g_maskbits[BB*NN*64];   // 64 words per row

__device__ __forceinline__ float dot4(float4 a, float4 b) {
    return a.x*b.x + a.y*b.y + a.z*b.z + a.w*b.w;
}
// ---- packed fp32x2 (FFMA2) helpers: exact fp32 semantics, 2 MACs/inst ----
__device__ __forceinline__ void fma2(u64& d, u64 a, u64 b) {
    asm("fma.rn.f32x2 %0, %1, %2, %0;" : "+l"(d) : "l"(a), "l"(b));
}
__device__ __forceinline__ void mul2(u64& d, u64 b) {
    asm("mul.rn.f32x2 %0, %0, %1;" : "+l"(d) : "l"(b));
}
__device__ __forceinline__ void add2(u64& d, u64 b) {
    asm("add.rn.f32x2 %0, %0, %1;" : "+l"(d) : "l"(b));
}
__device__ __forceinline__ u64 pack2(float p) {
    u64 r; asm("mov.b64 %0, {%1, %1};" : "=l"(r) : "f"(p)); return r;
}
__device__ __forceinline__ float hadd2(u64 v) {
    float lo, hi; asm("mov.b64 {%0, %1}, %2;" : "=f"(lo), "=f"(hi) : "l"(v));
    return lo + hi;
}
__device__ __forceinline__ void cp_async16(void* smem, const void* gmem) {
    unsigned s = (unsigned)__cvta_generic_to_shared(smem);
    asm volatile("cp.async.cg.shared.global [%0], [%1], 16;\n" :: "r"(s), "l"(gmem));
}
__device__ __forceinline__ void cp_commit() { asm volatile("cp.async.commit_group;\n"); }
template<int N> __device__ __forceinline__ void cp_wait() {
    asm volatile("cp.async.wait_group %0;\n" :: "n"(N));
}

// ---------------- 1) conv1d(SAME,K=3) + BN(eval) + ReLU -> g_hT ----------------
__global__ __launch_bounds__(256) void k_conv(const float* __restrict__ x,
                                              const float* __restrict__ cw,
                                              const float* __restrict__ cb,
                                              const float* __restrict__ bng,
                                              const float* __restrict__ bnb) {
    int node = blockIdx.x * 256 + threadIdx.x;
    int t = blockIdx.y;
    if (node >= BN) return;
    int b = node / NN, n = node - b * NN;
    const float* xb = x + b * (TT * NN) + n;
    float xm1 = (t > 0)      ? xb[(t - 1) * NN] : 0.f;
    float x0  =                xb[t * NN];
    float xp1 = (t < TT - 1) ? xb[(t + 1) * NN] : 0.f;
    float bns = rsqrtf(1.0f + 1e-5f);
#pragma unroll
    for (int f = 0; f < FF; f++) {
        float v = cw[f*3]*xm1 + cw[f*3+1]*x0 + cw[f*3+2]*xp1 + cb[f];
        v = v * (bng[f] * bns) + bnb[f];
        g_hT[(f * TT + t) * BN + node] = fmaxf(v, 0.f);
    }
}

// ---------------- 2) transpose proj_w [64][768] -> [768][64] ----------------
__global__ __launch_bounds__(256) void k_transw(const float* __restrict__ w) {
    int idx = blockIdx.x * 256 + threadIdx.x;
    if (idx < FT * HH) {
        int k = idx >> 6, h = idx & 63;
        g_projT[idx] = w[h * FT + k];
    }
}

// ---------------- 3) z = flat @ proj_w^T + b (tiled SGEMM, double-buffered, FFMA2) ----------------
__global__ __launch_bounds__(256) void k_proj(const float* __restrict__ pb) {
    __shared__ float Asm[2][32][64];
    __shared__ float Bsm[2][32][64];
    int t = threadIdx.x;
    int m0 = blockIdx.x * 64;
    int tx = t & 15, ty = t >> 4;
    int lrow0 = t >> 4, lcol0 = (t & 15) << 2;
    int lrow1 = (t + 256) >> 4, lcol1 = ((t + 256) & 15) << 2;
    u64 c2[4][2] = {};

    const int NT = FT / 32;  // 24
    cp_async16(&Asm[0][lrow0][lcol0], &g_hT[lrow0 * BN + m0 + lcol0]);
    cp_async16(&Asm[0][lrow1][lcol1], &g_hT[lrow1 * BN + m0 + lcol1]);
    cp_async16(&Bsm[0][lrow0][lcol0], &g_projT[lrow0 * HH + lcol0]);
    cp_async16(&Bsm[0][lrow1][lcol1], &g_projT[lrow1 * HH + lcol1]);
    cp_commit();

    for (int it = 0; it < NT; it++) {
        if (it + 1 < NT) {
            int k0 = (it + 1) * 32, nb = (it + 1) & 1;
            cp_async16(&Asm[nb][lrow0][lcol0], &g_hT[(k0 + lrow0) * BN + m0 + lcol0]);
            cp_async16(&Asm[nb][lrow1][lcol1], &g_hT[(k0 + lrow1) * BN + m0 + lcol1]);
            cp_async16(&Bsm[nb][lrow0][lcol0], &g_projT[(k0 + lrow0) * HH + lcol0]);
            cp_async16(&Bsm[nb][lrow1][lcol1], &g_projT[(k0 + lrow1) * HH + lcol1]);
            cp_commit();
            cp_wait<1>();
        } else {
            cp_wait<0>();
        }
        __syncthreads();
        int buf = it & 1;
#pragma unroll
        for (int kk = 0; kk < 32; kk++) {
            float4 a = *(float4*)&Asm[buf][kk][ty * 4];
            ulonglong2 bv = *(ulonglong2*)&Bsm[buf][kk][tx * 4];
            float av[4] = {a.x, a.y, a.z, a.w};
#pragma unroll
            for (int i = 0; i < 4; i++) {
                u64 a2 = pack2(av[i]);
                fma2(c2[i][0], a2, bv.x);
                fma2(c2[i][1], a2, bv.y);
            }
        }
        __syncthreads();
    }
    u64 pb0 = *(const u64*)&pb[tx * 4];
    u64 pb1 = *(const u64*)&pb[tx * 4 + 2];
#pragma unroll
    for (int i = 0; i < 4; i++) {
        add2(c2[i][0], pb0);
        add2(c2[i][1], pb1);
        ulonglong2 o; o.x = c2[i][0]; o.y = c2[i][1];
        *(ulonglong2*)&g_z[(m0 + ty * 4 + i) * HH + tx * 4] = o;
    }
}

// ---------------- 4) LayerNorm + ReLU -> g_node ----------------
__global__ __launch_bounds__(256) void k_ln1(const float* __restrict__ g,
                                             const float* __restrict__ bb) {
    int w = threadIdx.x >> 5, lane = threadIdx.x & 31;
    int m = blockIdx.x * 8 + w;
    float v0 = g_z[m * 64 + lane], v1 = g_z[m * 64 + 32 + lane];
    float s = v0 + v1;
#pragma unroll
    for (int off = 16; off; off >>= 1) s += __shfl_xor_sync(0xffffffffu, s, off);
    float mean = s * (1.f / 64.f);
    float d0 = v0 - mean, d1 = v1 - mean;
    float vs = d0 * d0 + d1 * d1;
#pragma unroll
    for (int off = 16; off; off >>= 1) vs += __shfl_xor_sync(0xffffffffu, vs, off);
    float rs = rsqrtf(vs * (1.f / 64.f) + 1e-5f);
    g_node[m * 64 + lane]      = fmaxf(d0 * rs * g[lane]      + bb[lane],      0.f);
    g_node[m * 64 + 32 + lane] = fmaxf(d1 * rs * g[lane + 32] + bb[lane + 32], 0.f);
}

// ---------------- 5) src/dst (leaky 0.2) + qkv, fused (FFMA2) ----------------
__global__ __launch_bounds__(256) void k_sdq(const float* __restrict__ sw, const float* __restrict__ sb,
                                             const float* __restrict__ dw, const float* __restrict__ db,
                                             const float* __restrict__ iw, const float* __restrict__ ib) {
    __shared__ float nsm[64 * 64];
    int t = threadIdx.x;
    int m0 = blockIdx.x * 64;
#pragma unroll
    for (int r = 0; r < 4; r++) {
        int idx = (t + 256 * r) * 4;
        *(float4*)&nsm[idx] = *(const float4*)&g_node[m0 * 64 + idx];
    }
    __syncthreads();
    const float* wrow; float bias;
    if (t < 32)       { wrow = sw + t * 64;        bias = sb[t]; }
    else if (t < 64)  { wrow = dw + (t - 32) * 64; bias = db[t - 32]; }
    else              { wrow = iw + (t - 64) * 64; bias = ib[t - 64]; }
    u64 wr[32];
#pragma unroll
    for (int r = 0; r < 16; r++) {
        ulonglong2 v = *(const ulonglong2*)&wrow[r * 4];
        wr[2*r] = v.x; wr[2*r+1] = v.y;
    }
    for (int m = 0; m < 64; m++) {
        u64 a = 0;
#pragma unroll
        for (int r = 0; r < 16; r++) {
            ulonglong2 nv = *(ulonglong2*)&nsm[m * 64 + r * 4];
            fma2(a, wr[2*r], nv.x);
            fma2(a, wr[2*r+1], nv.y);
        }
        float acc = hadd2(a) + bias;
        int gm = m0 + m;
        if (t < 64) {
            acc = (acc > 0.f) ? acc : 0.2f * acc;
            if (t < 32) g_src[gm * 32 + t] = acc;
            else        g_dst[gm * 32 + t - 32] = acc;
        } else {
            g_qkv[gm * 192 + t - 64] = acc;
        }
    }
}

// ---------------- 6) attention-1: 4 queries/warp, 128 threads, FFMA2 ----------------
__global__ __launch_bounds__(128) void k_attn1() {
    __shared__ float Ksm[2][128][20];
    __shared__ float Vsm[2][128][20];
    int t = threadIdx.x, w = t >> 5, lane = t & 31;
    int b = blockIdx.z, h = blockIdx.y;
    int q0 = blockIdx.x * 16 + w * 4;   // queries q0..q0+3
    const float* qkv_b = g_qkv + b * (NN * 192);
    u64 qp[4][8];
#pragma unroll
    for (int qq = 0; qq < 4; qq++) {
        const float* qptr = qkv_b + (q0 + qq) * 192 + h * 16;
#pragma unroll
        for (int r = 0; r < 4; r++) {
            ulonglong2 v = *(const ulonglong2*)&qptr[r * 4];
            qp[qq][2*r] = v.x; qp[qq][2*r+1] = v.y;
        }
    }
    const int NT = (NN + 127) / 128;  // 16

    auto prefetch = [&](int buf, int j0) {
        int row = j0 + t;
        if (row > NN - 1) row = NN - 1;
        const float* kp = qkv_b + row * 192 + 64 + h * 16;
        cp_async16(&Ksm[buf][t][0],  kp);
        cp_async16(&Ksm[buf][t][4],  kp + 4);
        cp_async16(&Ksm[buf][t][8],  kp + 8);
        cp_async16(&Ksm[buf][t][12], kp + 12);
        const float* vp = kp + 64;
        cp_async16(&Vsm[buf][t][0],  vp);
        cp_async16(&Vsm[buf][t][4],  vp + 4);
        cp_async16(&Vsm[buf][t][8],  vp + 8);
        cp_async16(&Vsm[buf][t][12], vp + 12);
    };

    prefetch(0, 0); cp_commit();

    float mx[4] = {-1e30f, -1e30f, -1e30f, -1e30f};
    float l[4] = {};
    u64 acc[4][8] = {};
    for (int it = 0; it < NT; it++) {
        int j0 = it * 128;
        if (it + 1 < NT) { prefetch((it + 1) & 1, j0 + 128); cp_commit(); cp_wait<1>(); }
        else             { cp_wait<0>(); }
        __syncthreads();
        int buf = it & 1;
        float s[4][4];
#pragma unroll
        for (int c = 0; c < 4; c++) {
            int jj = lane + 32 * c;
            ulonglong2 ka = *(ulonglong2*)&Ksm[buf][jj][0];
            ulonglong2 kb = *(ulonglong2*)&Ksm[buf][jj][4];
            ulonglong2 kc = *(ulonglong2*)&Ksm[buf][jj][8];
            ulonglong2 kd = *(ulonglong2*)&Ksm[buf][jj][12];
            u64 k[8] = {ka.x, ka.y, kb.x, kb.y, kc.x, kc.y, kd.x, kd.y};
            bool oob = (j0 + jj >= NN);
#pragma unroll
            for (int qq = 0; qq < 4; qq++) {
                u64 d2 = 0;
#pragma unroll
                for (int r = 0; r < 8; r++) fma2(d2, qp[qq][r], k[r]);
                s[qq][c] = oob ? -1e30f : 0.25f * hadd2(d2);
            }
        }
        float t4[4];
#pragma unroll
        for (int qq = 0; qq < 4; qq++)
            t4[qq] = fmaxf(fmaxf(s[qq][0], s[qq][1]), fmaxf(s[qq][2], s[qq][3]));
#pragma unroll
        for (int off = 16; off; off >>= 1) {
#pragma unroll
            for (int qq = 0; qq < 4; qq++)
                t4[qq] = fmaxf(t4[qq], __shfl_xor_sync(0xffffffffu, t4[qq], off));
        }
#pragma unroll
        for (int qq = 0; qq < 4; qq++) {
            if (t4[qq] > mx[qq]) {
                float f = __expf(mx[qq] - t4[qq]);
                l[qq] *= f;
                u64 f2 = pack2(f);
#pragma unroll
                for (int r = 0; r < 8; r++) mul2(acc[qq][r], f2);
                mx[qq] = t4[qq];
            }
        }
#pragma unroll
        for (int c = 0; c < 4; c++) {
            int jj = lane + 32 * c;
            ulonglong2 va = *(ulonglong2*)&Vsm[buf][jj][0];
            ulonglong2 vb = *(ulonglong2*)&Vsm[buf][jj][4];
            ulonglong2 vc = *(ulonglong2*)&Vsm[buf][jj][8];
            ulonglong2 vd = *(ulonglong2*)&Vsm[buf][jj][12];
            u64 v[8] = {va.x, va.y, vb.x, vb.y, vc.x, vc.y, vd.x, vd.y};
#pragma unroll
            for (int qq = 0; qq < 4; qq++) {
                float p = __expf(s[qq][c] - mx[qq]);
                l[qq] += p;
                u64 p2 = pack2(p);
#pragma unroll
                for (int r = 0; r < 8; r++) fma2(acc[qq][r], p2, v[r]);
            }
        }
        __syncthreads();
    }
#pragma unroll
    for (int off = 16; off; off >>= 1) {
#pragma unroll
        for (int qq = 0; qq < 4; qq++) {
            l[qq] += __shfl_xor_sync(0xffffffffu, l[qq], off);
#pragma unroll
            for (int r = 0; r < 8; r++) {
                u64 o = __shfl_xor_sync(0xffffffffu, acc[qq][r], off);
                add2(acc[qq][r], o);
            }
        }
    }
    if (lane == 0) {
#pragma unroll
        for (int qq = 0; qq < 4; qq++) {
            u64 i2 = pack2(1.f / l[qq]);
#pragma unroll
            for (int r = 0; r < 8; r++) mul2(acc[qq][r], i2);
            float* op = g_yattn + (b * NN + q0 + qq) * 64 + h * 16;
#pragma unroll
            for (int r = 0; r < 4; r++) {
                ulonglong2 o; o.x = acc[qq][2*r]; o.y = acc[qq][2*r+1];
                *(ulonglong2*)&op[r * 4] = o;
            }
        }
    }
}

// ---------------- 7) out projection y = y_attn @ out_w^T + out_b (FFMA2) ----------------
__global__ __launch_bounds__(256) void k_outp(const float* __restrict__ ow,
                                              const float* __restrict__ ob) {
    __shared__ float ysm[64 * 64];
    int t = threadIdx.x;
    int m0 = blockIdx.x * 64;
#pragma unroll
    for (int r = 0; r < 4; r++) {
        int idx = (t + 256 * r) * 4;
        *(float4*)&ysm[idx] = *(const float4*)&g_yattn[m0 * 64 + idx];
    }
    __syncthreads();
    int o = t & 63, gq = t >> 6;
    u64 wr[32];
#pragma unroll
    for (int r = 0; r < 16; r++) {
        ulonglong2 v = *(const ulonglong2*)&ow[o * 64 + r * 4];
        wr[2*r] = v.x; wr[2*r+1] = v.y;
    }
    float bias = ob[o];
    for (int rr = 0; rr < 16; rr++) {
        int mm = gq * 16 + rr;
        u64 a = 0;
#pragma unroll
        for (int r = 0; r < 16; r++) {
            ulonglong2 nv = *(ulonglong2*)&ysm[mm * 64 + r * 4];
            fma2(a, wr[2*r], nv.x);
            fma2(a, wr[2*r+1], nv.y);
        }
        g_y[(m0 + mm) * 64 + o] = hadd2(a) + bias;
    }
}

// ---------------- 8) adjacency mask bits: SINGLE pass + diagonal fixup ----------------
// Off-diagonal: adj/norm + I <= 0  <=>  s*scale <= 0   (norm > 0 preserves sign)
// Diagonal:     s_qq*scale/norm + 1 <= 0  <=>  s_qq*scale <= -norm_q
__global__ __launch_bounds__(256) void k_mask(const float* __restrict__ es) {
    __shared__ float ssm[32][36];
    __shared__ float dsm[2][64][36];
    __shared__ float diagsm[32];
    int t = threadIdx.x, w = t >> 5, lane = t & 31;
    int b = blockIdx.y;
    int q0 = blockIdx.x * 32;
    float scale = es[0];
    {
        int row = t >> 3, col = (t & 7) << 2;
        int q = q0 + row;
        float4 v = make_float4(0.f, 0.f, 0.f, 0.f);
        if (q < NN) v = *(const float4*)&g_src[(b * NN + q) * 32 + col];
        *(float4*)&ssm[row][col] = v;
    }
    int lrow0 = t >> 3, lcol0 = (t & 7) << 2;
    int lrow1 = (t + 256) >> 3, lcol1 = ((t + 256) & 7) << 2;
    auto prefetch = [&](int buf, int j0) {
        int r0 = j0 + lrow0; if (r0 > NN - 1) r0 = NN - 1;
        int r1 = j0 + lrow1; if (r1 > NN - 1) r1 = NN - 1;
        cp_async16(&dsm[buf][lrow0][lcol0], &g_dst[(b * NN + r0) * 32 + lcol0]);
        cp_async16(&dsm[buf][lrow1][lcol1], &g_dst[(b * NN + r1) * 32 + lcol1]);
    };
    __syncthreads();
    // hoist this warp's 4 query rows into registers
    u64 qu[4][16];
#pragma unroll
    for (int c = 0; c < 4; c++) {
#pragma unroll
        for (int r = 0; r < 8; r++) {
            ulonglong2 v = *(ulonglong2*)&ssm[w * 4 + c][r * 4];
            qu[c][2*r] = v.x; qu[c][2*r+1] = v.y;
        }
    }

    const int NJT = 32;
    prefetch(0, 0); cp_commit();
    float sumsq[4] = {};
    for (int jt = 0; jt < NJT; jt++) {
        int j0 = jt * 64;
        if (jt + 1 < NJT) { prefetch((jt + 1) & 1, j0 + 64); cp_commit(); cp_wait<1>(); }
        else              { cp_wait<0>(); }
        __syncthreads();
        int buf = jt & 1;
#pragma unroll
        for (int half = 0; half < 2; half++) {
            int jj = lane + 32 * half;
            u64 dv[16];
#pragma unroll
            for (int r = 0; r < 8; r++) {
                ulonglong2 v = *(ulonglong2*)&dsm[buf][jj][r * 4];
                dv[2*r] = v.x; dv[2*r+1] = v.y;
            }
            bool valid = (j0 + jj < NN);
#pragma unroll
            for (int c = 0; c < 4; c++) {
                int q = q0 + w * 4 + c;
                u64 a = 0;
#pragma unroll
                for (int r = 0; r < 16; r++) fma2(a, qu[c][r], dv[r]);
                float s = hadd2(a);
                unsigned word = __ballot_sync(0xffffffffu, s * scale <= 0.f);
                if (lane == 0 && q < NN) g_maskbits[(b * NN + q) * 64 + jt * 2 + half] = word;
                if (valid) sumsq[c] += s * s;
                if (j0 + jj == q) diagsm[w * 4 + c] = s;
            }
        }
        __syncthreads();
    }
    // reduce row sumsq; fix up the diagonal bit (same thread wrote that word)
#pragma unroll
    for (int c = 0; c < 4; c++) {
        float red = sumsq[c];
#pragma unroll
        for (int off = 16; off; off >>= 1) red += __shfl_xor_sync(0xffffffffu, red, off);
        if (lane == 0) {
            int qq = w * 4 + c;
            int q = q0 + qq;
            if (q < NN) {
                float norm = fmaxf(sqrtf(red) * fabsf(scale), 1e-12f);
                float sd = diagsm[qq];
                bool bit = (sd * scale <= -norm);
                unsigned idx = (b * NN + q) * 64 + (q >> 5);
                unsigned word = g_maskbits[idx];
                unsigned msk = 1u << (q & 31);
                g_maskbits[idx] = bit ? (word | msk) : (word & ~msk);
            }
        }
    }
}

// ---------------- 9) attention-2: 2 queries/warp, half-warp PV, FFMA2 ----------------
__global__ __launch_bounds__(256) void k_attn2() {
    __shared__ float ysm[2][64][68];
    __shared__ float qsm[16][68];
    __shared__ float psm[8][2][64];
    int t = threadIdx.x, w = t >> 5, lane = t & 31;
    int b = blockIdx.y;
    int qA = blockIdx.x * 16 + w * 2;
    int qB = qA + 1;
    const float* yb = g_y + b * (NN * 64);
    const unsigned* mrowA = g_maskbits + (b * NN + qA) * 64;
    const unsigned* mrowB = g_maskbits + (b * NN + qB) * 64;
    {
        int row = t >> 4, col = (t & 15) << 2;
        *(float4*)&qsm[row][col] = *(const float4*)&yb[(blockIdx.x * 16 + row) * 64 + col];
    }

    int lrow0 = t >> 4, lcol0 = (t & 15) << 2;
    auto prefetch = [&](int buf, int j0) {
#pragma unroll
        for (int r = 0; r < 4; r++) {
            int row = lrow0 + 16 * r;
            int grow = j0 + row; if (grow > NN - 1) grow = NN - 1;
            cp_async16(&ysm[buf][row][lcol0], &yb[grow * 64 + lcol0]);
        }
    };

    const int NT = (NN + 63) / 64;  // 32
    prefetch(0, 0); cp_commit();

    float mxA = -1e30f, mxB = -1e30f;
    float lA = 0.f, lB = 0.f;
    u64 accP[32] = {};
    int hq = lane >> 4, hl = lane & 15;

    for (int it = 0; it < NT; it++) {
        int j0 = it * 64;
        if (it + 1 < NT) { prefetch((it + 1) & 1, j0 + 64); cp_commit(); cp_wait<1>(); }
        else             { cp_wait<0>(); }
        __syncthreads();
        int buf = it & 1;
        u64 A0 = 0, A1 = 0, B0 = 0, B1 = 0;
#pragma unroll
        for (int r = 0; r < 16; r++) {
            ulonglong2 k0 = *(ulonglong2*)&ysm[buf][lane][r * 4];
            ulonglong2 k1 = *(ulonglong2*)&ysm[buf][lane + 32][r * 4];
            ulonglong2 qa = *(ulonglong2*)&qsm[w * 2][r * 4];
            ulonglong2 qb = *(ulonglong2*)&qsm[w * 2 + 1][r * 4];
            fma2(A0, qa.x, k0.x); fma2(A0, qa.y, k0.y);
            fma2(A1, qa.x, k1.x); fma2(A1, qa.y, k1.y);
            fma2(B0, qb.x, k0.x); fma2(B0, qb.y, k0.y);
            fma2(B1, qb.x, k1.x); fma2(B1, qb.y, k1.y);
        }
        float sA0 = hadd2(A0), sA1 = hadd2(A1), sB0 = hadd2(B0), sB1 = hadd2(B1);
        unsigned wA0 = mrowA[it * 2], wA1 = mrowA[it * 2 + 1];
        unsigned wB0 = mrowB[it * 2], wB1 = mrowB[it * 2 + 1];
        sA0 = sA0 * 0.125f + (((wA0 >> lane) & 1u) ? -1e9f : 0.f);
        sA1 = sA1 * 0.125f + (((wA1 >> lane) & 1u) ? -1e9f : 0.f);
        sB0 = sB0 * 0.125f + (((wB0 >> lane) & 1u) ? -1e9f : 0.f);
        sB1 = sB1 * 0.125f + (((wB1 >> lane) & 1u) ? -1e9f : 0.f);
        if (j0 + lane >= NN)      { sA0 = -1e30f; sB0 = -1e30f; }
        if (j0 + 32 + lane >= NN) { sA1 = -1e30f; sB1 = -1e30f; }
        float tA = fmaxf(sA0, sA1), tB = fmaxf(sB0, sB1);
#pragma unroll
        for (int off = 16; off; off >>= 1) {
            tA = fmaxf(tA, __shfl_xor_sync(0xffffffffu, tA, off));
            tB = fmaxf(tB, __shfl_xor_sync(0xffffffffu, tB, off));
        }
        bool rsA = (tA > mxA), rsB = (tB > mxB);
        float fA = rsA ? __expf(mxA - tA) : 1.f;
        float fB = rsB ? __expf(mxB - tB) : 1.f;
        if (rsA) { lA *= fA; mxA = tA; }
        if (rsB) { lB *= fB; mxB = tB; }
        if (rsA || rsB) {
            u64 f2 = pack2(hq ? fB : fA);
#pragma unroll
            for (int r = 0; r < 32; r++) mul2(accP[r], f2);
        }
        float pA0 = __expf(sA0 - mxA), pA1 = __expf(sA1 - mxA);
        float pB0 = __expf(sB0 - mxB), pB1 = __expf(sB1 - mxB);
        lA += pA0 + pA1; lB += pB0 + pB1;
        psm[w][0][lane]      = pA0;
        psm[w][0][lane + 32] = pA1;
        psm[w][1][lane]      = pB0;
        psm[w][1][lane + 32] = pB1;
        __syncwarp();
        const float* pp = &psm[w][hq][0];
#pragma unroll
        for (int c = 0; c < 4; c++) {
            int j = hl + 16 * c;
            u64 p2 = pack2(pp[j]);
#pragma unroll
            for (int r = 0; r < 16; r++) {
                ulonglong2 v = *(ulonglong2*)&ysm[buf][j][r * 4];
                fma2(accP[2*r],   p2, v.x);
                fma2(accP[2*r+1], p2, v.y);
            }
        }
        __syncthreads();
    }
#pragma unroll
    for (int off = 16; off; off >>= 1) {
        lA += __shfl_xor_sync(0xffffffffu, lA, off);
        lB += __shfl_xor_sync(0xffffffffu, lB, off);
    }
    float inv = 1.f / (hq ? lB : lA);
#pragma unroll
    for (int r = 0; r < 16; r++) {
        u64 send = (hl & 8) ? accP[r] : accP[r + 16];
        u64 oth = __shfl_xor_sync(0xffffffffu, send, 8);
        u64 keep = (hl & 8) ? accP[r + 16] : accP[r];
        add2(keep, oth); accP[r] = keep;
    }
#pragma unroll
    for (int r = 0; r < 8; r++) {
        u64 send = (hl & 4) ? accP[r] : accP[r + 8];
        u64 oth = __shfl_xor_sync(0xffffffffu, send, 4);
        u64 keep = (hl & 4) ? accP[r + 8] : accP[r];
        add2(keep, oth); accP[r] = keep;
    }
#pragma unroll
    for (int r = 0; r < 4; r++) {
        u64 send = (hl & 2) ? accP[r] : accP[r + 4];
        u64 oth = __shfl_xor_sync(0xffffffffu, send, 2);
        u64 keep = (hl & 2) ? accP[r + 4] : accP[r];
        add2(keep, oth); accP[r] = keep;
    }
#pragma unroll
    for (int r = 0; r < 2; r++) {
        u64 send = (hl & 1) ? accP[r] : accP[r + 2];
        u64 oth = __shfl_xor_sync(0xffffffffu, send, 1);
        u64 keep = (hl & 1) ? accP[r + 2] : accP[r];
        add2(keep, oth); accP[r] = keep;
    }
    u64 i2 = pack2(inv);
    mul2(accP[0], i2); mul2(accP[1], i2);
    int q = hq ? qB : qA;
    ulonglong2 o; o.x = accP[0]; o.y = accP[1];
    *(ulonglong2*)&g_y2[(b * NN + q) * 64 + 4 * hl] = o;
}

// ---------------- 10) residual + LN(lnA) + horizon predictor ----------------
__global__ __launch_bounds__(256) void k_final(const float* __restrict__ lg,
                                               const float* __restrict__ lb,
                                               const float* __restrict__ pw,
                                               const float* __restrict__ pb,
                                               float* __restrict__ out) {
    __shared__ float rsm[8][64];
    __shared__ float pwsm[64 * 24];
    int t = threadIdx.x, w = t >> 5, lane = t & 31;
    int m = blockIdx.x * 8 + w;
    for (int idx = t; idx < 24 * 64; idx += 256) {
        int o = idx >> 6, d = idx & 63;
        pwsm[d * 24 + o] = pw[idx];
    }
    float v0 = g_y2[m * 64 + lane]      + g_node[m * 64 + lane];
    float v1 = g_y2[m * 64 + 32 + lane] + g_node[m * 64 + 32 + lane];
    float s = v0 + v1;
#pragma unroll
    for (int off = 16; off; off >>= 1) s += __shfl_xor_sync(0xffffffffu, s, off);
    float mean = s * (1.f / 64.f);
    float d0 = v0 - mean, d1 = v1 - mean;
    float vs = d0 * d0 + d1 * d1;
#pragma unroll
    for (int off = 16; off; off >>= 1) vs += __shfl_xor_sync(0xffffffffu, vs, off);
    float rs = rsqrtf(vs * (1.f / 64.f) + 1e-5f);
    rsm[w][lane]      = d0 * rs * lg[lane]      + lb[lane];
    rsm[w][lane + 32] = d1 * rs * lg[lane + 32] + lb[lane + 32];
    __syncthreads();
    if (lane < 24) {
        float acc = pb[lane];
#pragma unroll
        for (int d = 0; d < 64; d++) acc += rsm[w][d] * pwsm[d * 24 + lane];
        out[m * 24 + lane] = acc;
    }
}

// ---------------- launch ----------------
extern "C" void kernel_launch(void* const* d_in, const int* in_sizes, int n_in,
                              void* d_out, int out_size) {
    const float* x        = (const float*)d_in[0];
    const float* conv_w   = (const float*)d_in[1];
    const float* conv_b   = (const float*)d_in[2];
    const float* bn_g     = (const float*)d_in[3];
    const float* bn_b     = (const float*)d_in[4];
    const float* proj_w   = (const float*)d_in[5];
    const float* proj_b   = (const float*)d_in[6];
    const float* ln1_g    = (const float*)d_in[7];
    const float* ln1_b    = (const float*)d_in[8];
    const float* src_w    = (const float*)d_in[9];
    const float* src_b    = (const float*)d_in[10];
    const float* dst_w    = (const float*)d_in[11];
    const float* dst_b    = (const float*)d_in[12];
    const float* edge_sc  = (const float*)d_in[13];
    const float* inp_w    = (const float*)d_in[14];
    const float* inp_b    = (const float*)d_in[15];
    const float* out_w    = (const float*)d_in[16];
    const float* out_b    = (const float*)d_in[17];
    const float* lnA_g    = (const float*)d_in[18];
    const float* lnA_b    = (const float*)d_in[19];
    const float* pred_w   = (const float*)d_in[20];
    const float* pred_b   = (const float*)d_in[21];
    float* out = (float*)d_out;

    k_conv<<<dim3((BN + 255) / 256, TT), 256>>>(x, conv_w, conv_b, bn_g, bn_b);
    k_transw<<<(FT * HH + 255) / 256, 256>>>(proj_w);
    k_proj<<<BN / 64, 256>>>(proj_b);
    k_ln1<<<BN / 8, 256>>>(ln1_g, ln1_b);
    k_sdq<<<BN / 64, 256>>>(src_w, src_b, dst_w, dst_b, inp_w, inp_b);
    k_attn1<<<dim3(NN / 16, NHEADS, BB), 128>>>();
    k_outp<<<BN / 64, 256>>>(out_w, out_b);
    k_mask<<<dim3((NN + 31) / 32, BB), 256>>>(edge_sc);
    k_attn2<<<dim3(NN / 16, BB), 256>>>();
    k_final<<<BN / 8, 256>>>(lnA_g, lnA_b, pred_w, pred_b, out);
}

// round 7
// speedup vs baseline: 2.2783x; 1.0522x over previous
#include <cuda_runtime.h>
#include <math.h>

#define BB 4
#define TT 48
#define NN 2000
#define BN (BB*NN)      // 8000
#define FF 16
#define HH 64
#define NHEADS 4
#define HD 16
#define HOR 24
#define PP 32
#define FT (FF*TT)      // 768

typedef unsigned long long u64;

// ---------------- scratch (device globals: no allocation) ----------------
__device__ float g_hT[FT*BN];      // conv features, k-major [768][8000]
__device__ float g_projT[FT*HH];   // proj_w transposed [768][64]
__device__ float g_z[BN*HH];
__device__ float g_node[BN*HH];
__device__ float g_src[BN*PP];
__device__ float g_dst[BN*PP];
__device__ float g_qkv[BN*3*HH];
__device__ float g_yattn[BN*HH];
__device__ float g_y[BN*HH];
__device__ float g_y2[BN*HH];
__device__ unsigned g_maskbits[BB*NN*64];   // 64 words per row

// ---- packed fp32x2 (FFMA2) helpers: exact fp32 semantics, 2 MACs/inst ----
__device__ __forceinline__ void fma2(u64& d, u64 a, u64 b) {
    asm("fma.rn.f32x2 %0, %1, %2, %0;" : "+l"(d) : "l"(a), "l"(b));
}
__device__ __forceinline__ void mul2(u64& d, u64 b) {
    asm("mul.rn.f32x2 %0, %0, %1;" : "+l"(d) : "l"(b));
}
__device__ __forceinline__ void add2(u64& d, u64 b) {
    asm("add.rn.f32x2 %0, %0, %1;" : "+l"(d) : "l"(b));
}
__device__ __forceinline__ u64 pack2(float p) {
    u64 r; asm("mov.b64 %0, {%1, %1};" : "=l"(r) : "f"(p)); return r;
}
__device__ __forceinline__ float hadd2(u64 v) {
    float lo, hi; asm("mov.b64 {%0, %1}, %2;" : "=f"(lo), "=f"(hi) : "l"(v));
    return lo + hi;
}
__device__ __forceinline__ void cp_async16(void* smem, const void* gmem) {
    unsigned s = (unsigned)__cvta_generic_to_shared(smem);
    asm volatile("cp.async.cg.shared.global [%0], [%1], 16;\n" :: "r"(s), "l"(gmem));
}
__device__ __forceinline__ void cp_commit() { asm volatile("cp.async.commit_group;\n"); }
template<int N> __device__ __forceinline__ void cp_wait() {
    asm volatile("cp.async.wait_group %0;\n" :: "n"(N));
}

// ---------------- 1) conv1d(SAME,K=3) + BN(eval) + ReLU -> g_hT ----------------
__global__ __launch_bounds__(256) void k_conv(const float* __restrict__ x,
                                              const float* __restrict__ cw,
                                              const float* __restrict__ cb,
                                              const float* __restrict__ bng,
                                              const float* __restrict__ bnb) {
    int node = blockIdx.x * 256 + threadIdx.x;
    int t = blockIdx.y;
    if (node >= BN) return;
    int b = node / NN, n = node - b * NN;
    const float* xb = x + b * (TT * NN) + n;
    float xm1 = (t > 0)      ? xb[(t - 1) * NN] : 0.f;
    float x0  =                xb[t * NN];
    float xp1 = (t < TT - 1) ? xb[(t + 1) * NN] : 0.f;
    float bns = rsqrtf(1.0f + 1e-5f);
#pragma unroll
    for (int f = 0; f < FF; f++) {
        float v = cw[f*3]*xm1 + cw[f*3+1]*x0 + cw[f*3+2]*xp1 + cb[f];
        v = v * (bng[f] * bns) + bnb[f];
        g_hT[(f * TT + t) * BN + node] = fmaxf(v, 0.f);
    }
}

// ---------------- 2) transpose proj_w [64][768] -> [768][64] ----------------
__global__ __launch_bounds__(256) void k_transw(const float* __restrict__ w) {
    int idx = blockIdx.x * 256 + threadIdx.x;
    if (idx < FT * HH) {
        int k = idx >> 6, h = idx & 63;
        g_projT[idx] = w[h * FT + k];
    }
}

// ---------------- 3) z = flat @ proj_w^T + b (tiled SGEMM, double-buffered, FFMA2) ----------------
__global__ __launch_bounds__(256) void k_proj(const float* __restrict__ pb) {
    __shared__ float Asm[2][32][64];
    __shared__ float Bsm[2][32][64];
    int t = threadIdx.x;
    int m0 = blockIdx.x * 64;
    int tx = t & 15, ty = t >> 4;
    int lrow0 = t >> 4, lcol0 = (t & 15) << 2;
    int lrow1 = (t + 256) >> 4, lcol1 = ((t + 256) & 15) << 2;
    u64 c2[4][2] = {};

    const int NT = FT / 32;  // 24
    cp_async16(&Asm[0][lrow0][lcol0], &g_hT[lrow0 * BN + m0 + lcol0]);
    cp_async16(&Asm[0][lrow1][lcol1], &g_hT[lrow1 * BN + m0 + lcol1]);
    cp_async16(&Bsm[0][lrow0][lcol0], &g_projT[lrow0 * HH + lcol0]);
    cp_async16(&Bsm[0][lrow1][lcol1], &g_projT[lrow1 * HH + lcol1]);
    cp_commit();

    for (int it = 0; it < NT; it++) {
        if (it + 1 < NT) {
            int k0 = (it + 1) * 32, nb = (it + 1) & 1;
            cp_async16(&Asm[nb][lrow0][lcol0], &g_hT[(k0 + lrow0) * BN + m0 + lcol0]);
            cp_async16(&Asm[nb][lrow1][lcol1], &g_hT[(k0 + lrow1) * BN + m0 + lcol1]);
            cp_async16(&Bsm[nb][lrow0][lcol0], &g_projT[(k0 + lrow0) * HH + lcol0]);
            cp_async16(&Bsm[nb][lrow1][lcol1], &g_projT[(k0 + lrow1) * HH + lcol1]);
            cp_commit();
            cp_wait<1>();
        } else {
            cp_wait<0>();
        }
        __syncthreads();
        int buf = it & 1;
#pragma unroll
        for (int kk = 0; kk < 32; kk++) {
            float4 a = *(float4*)&Asm[buf][kk][ty * 4];
            ulonglong2 bv = *(ulonglong2*)&Bsm[buf][kk][tx * 4];
            float av[4] = {a.x, a.y, a.z, a.w};
#pragma unroll
            for (int i = 0; i < 4; i++) {
                u64 a2 = pack2(av[i]);
                fma2(c2[i][0], a2, bv.x);
                fma2(c2[i][1], a2, bv.y);
            }
        }
        __syncthreads();
    }
    u64 pb0 = *(const u64*)&pb[tx * 4];
    u64 pb1 = *(const u64*)&pb[tx * 4 + 2];
#pragma unroll
    for (int i = 0; i < 4; i++) {
        add2(c2[i][0], pb0);
        add2(c2[i][1], pb1);
        ulonglong2 o; o.x = c2[i][0]; o.y = c2[i][1];
        *(ulonglong2*)&g_z[(m0 + ty * 4 + i) * HH + tx * 4] = o;
    }
}

// ---------------- 4) LayerNorm + ReLU -> g_node ----------------
__global__ __launch_bounds__(256) void k_ln1(const float* __restrict__ g,
                                             const float* __restrict__ bb) {
    int w = threadIdx.x >> 5, lane = threadIdx.x & 31;
    int m = blockIdx.x * 8 + w;
    float v0 = g_z[m * 64 + lane], v1 = g_z[m * 64 + 32 + lane];
    float s = v0 + v1;
#pragma unroll
    for (int off = 16; off; off >>= 1) s += __shfl_xor_sync(0xffffffffu, s, off);
    float mean = s * (1.f / 64.f);
    float d0 = v0 - mean, d1 = v1 - mean;
    float vs = d0 * d0 + d1 * d1;
#pragma unroll
    for (int off = 16; off; off >>= 1) vs += __shfl_xor_sync(0xffffffffu, vs, off);
    float rs = rsqrtf(vs * (1.f / 64.f) + 1e-5f);
    g_node[m * 64 + lane]      = fmaxf(d0 * rs * g[lane]      + bb[lane],      0.f);
    g_node[m * 64 + 32 + lane] = fmaxf(d1 * rs * g[lane + 32] + bb[lane + 32], 0.f);
}

// ---------------- 5) src/dst (leaky 0.2) + qkv, fused (FFMA2) ----------------
__global__ __launch_bounds__(256) void k_sdq(const float* __restrict__ sw, const float* __restrict__ sb,
                                             const float* __restrict__ dw, const float* __restrict__ db,
                                             const float* __restrict__ iw, const float* __restrict__ ib) {
    __shared__ float nsm[64 * 64];
    int t = threadIdx.x;
    int m0 = blockIdx.x * 64;
#pragma unroll
    for (int r = 0; r < 4; r++) {
        int idx = (t + 256 * r) * 4;
        *(float4*)&nsm[idx] = *(const float4*)&g_node[m0 * 64 + idx];
    }
    __syncthreads();
    const float* wrow; float bias;
    if (t < 32)       { wrow = sw + t * 64;        bias = sb[t]; }
    else if (t < 64)  { wrow = dw + (t - 32) * 64; bias = db[t - 32]; }
    else              { wrow = iw + (t - 64) * 64; bias = ib[t - 64]; }
    u64 wr[32];
#pragma unroll
    for (int r = 0; r < 16; r++) {
        ulonglong2 v = *(const ulonglong2*)&wrow[r * 4];
        wr[2*r] = v.x; wr[2*r+1] = v.y;
    }
    for (int m = 0; m < 64; m++) {
        u64 a = 0;
#pragma unroll
        for (int r = 0; r < 16; r++) {
            ulonglong2 nv = *(ulonglong2*)&nsm[m * 64 + r * 4];
            fma2(a, wr[2*r], nv.x);
            fma2(a, wr[2*r+1], nv.y);
        }
        float acc = hadd2(a) + bias;
        int gm = m0 + m;
        if (t < 64) {
            acc = (acc > 0.f) ? acc : 0.2f * acc;
            if (t < 32) g_src[gm * 32 + t] = acc;
            else        g_dst[gm * 32 + t - 32] = acc;
        } else {
            g_qkv[gm * 192 + t - 64] = acc;
        }
    }
}

// ---------------- 6) attention-1: 4 queries/warp, 128 threads, FFMA2 ----------------
__global__ __launch_bounds__(128) void k_attn1() {
    __shared__ float Ksm[2][128][20];
    __shared__ float Vsm[2][128][20];
    int t = threadIdx.x, w = t >> 5, lane = t & 31;
    int b = blockIdx.z, h = blockIdx.y;
    int q0 = blockIdx.x * 16 + w * 4;   // queries q0..q0+3
    const float* qkv_b = g_qkv + b * (NN * 192);
    u64 qp[4][8];
#pragma unroll
    for (int qq = 0; qq < 4; qq++) {
        const float* qptr = qkv_b + (q0 + qq) * 192 + h * 16;
#pragma unroll
        for (int r = 0; r < 4; r++) {
            ulonglong2 v = *(const ulonglong2*)&qptr[r * 4];
            qp[qq][2*r] = v.x; qp[qq][2*r+1] = v.y;
        }
    }
    const int NT = (NN + 127) / 128;  // 16

    auto prefetch = [&](int buf, int j0) {
        int row = j0 + t;
        if (row > NN - 1) row = NN - 1;
        const float* kp = qkv_b + row * 192 + 64 + h * 16;
        cp_async16(&Ksm[buf][t][0],  kp);
        cp_async16(&Ksm[buf][t][4],  kp + 4);
        cp_async16(&Ksm[buf][t][8],  kp + 8);
        cp_async16(&Ksm[buf][t][12], kp + 12);
        const float* vp = kp + 64;
        cp_async16(&Vsm[buf][t][0],  vp);
        cp_async16(&Vsm[buf][t][4],  vp + 4);
        cp_async16(&Vsm[buf][t][8],  vp + 8);
        cp_async16(&Vsm[buf][t][12], vp + 12);
    };

    prefetch(0, 0); cp_commit();

    float mx[4] = {-1e30f, -1e30f, -1e30f, -1e30f};
    float l[4] = {};
    u64 acc[4][8] = {};
    for (int it = 0; it < NT; it++) {
        int j0 = it * 128;
        if (it + 1 < NT) { prefetch((it + 1) & 1, j0 + 128); cp_commit(); cp_wait<1>(); }
        else             { cp_wait<0>(); }
        __syncthreads();
        int buf = it & 1;
        float s[4][4];
#pragma unroll
        for (int c = 0; c < 4; c++) {
            int jj = lane + 32 * c;
            ulonglong2 ka = *(ulonglong2*)&Ksm[buf][jj][0];
            ulonglong2 kb = *(ulonglong2*)&Ksm[buf][jj][4];
            ulonglong2 kc = *(ulonglong2*)&Ksm[buf][jj][8];
            ulonglong2 kd = *(ulonglong2*)&Ksm[buf][jj][12];
            u64 k[8] = {ka.x, ka.y, kb.x, kb.y, kc.x, kc.y, kd.x, kd.y};
            bool oob = (j0 + jj >= NN);
#pragma unroll
            for (int qq = 0; qq < 4; qq++) {
                u64 d2 = 0;
#pragma unroll
                for (int r = 0; r < 8; r++) fma2(d2, qp[qq][r], k[r]);
                s[qq][c] = oob ? -1e30f : 0.25f * hadd2(d2);
            }
        }
        float t4[4];
#pragma unroll
        for (int qq = 0; qq < 4; qq++)
            t4[qq] = fmaxf(fmaxf(s[qq][0], s[qq][1]), fmaxf(s[qq][2], s[qq][3]));
#pragma unroll
        for (int off = 16; off; off >>= 1) {
#pragma unroll
            for (int qq = 0; qq < 4; qq++)
                t4[qq] = fmaxf(t4[qq], __shfl_xor_sync(0xffffffffu, t4[qq], off));
        }
#pragma unroll
        for (int qq = 0; qq < 4; qq++) {
            if (t4[qq] > mx[qq]) {
                float f = __expf(mx[qq] - t4[qq]);
                l[qq] *= f;
                u64 f2 = pack2(f);
#pragma unroll
                for (int r = 0; r < 8; r++) mul2(acc[qq][r], f2);
                mx[qq] = t4[qq];
            }
        }
#pragma unroll
        for (int c = 0; c < 4; c++) {
            int jj = lane + 32 * c;
            ulonglong2 va = *(ulonglong2*)&Vsm[buf][jj][0];
            ulonglong2 vb = *(ulonglong2*)&Vsm[buf][jj][4];
            ulonglong2 vc = *(ulonglong2*)&Vsm[buf][jj][8];
            ulonglong2 vd = *(ulonglong2*)&Vsm[buf][jj][12];
            u64 v[8] = {va.x, va.y, vb.x, vb.y, vc.x, vc.y, vd.x, vd.y};
#pragma unroll
            for (int qq = 0; qq < 4; qq++) {
                float p = __expf(s[qq][c] - mx[qq]);
                l[qq] += p;
                u64 p2 = pack2(p);
#pragma unroll
                for (int r = 0; r < 8; r++) fma2(acc[qq][r], p2, v[r]);
            }
        }
        __syncthreads();
    }
#pragma unroll
    for (int off = 16; off; off >>= 1) {
#pragma unroll
        for (int qq = 0; qq < 4; qq++) {
            l[qq] += __shfl_xor_sync(0xffffffffu, l[qq], off);
#pragma unroll
            for (int r = 0; r < 8; r++) {
                u64 o = __shfl_xor_sync(0xffffffffu, acc[qq][r], off);
                add2(acc[qq][r], o);
            }
        }
    }
    if (lane == 0) {
#pragma unroll
        for (int qq = 0; qq < 4; qq++) {
            u64 i2 = pack2(1.f / l[qq]);
#pragma unroll
            for (int r = 0; r < 8; r++) mul2(acc[qq][r], i2);
            float* op = g_yattn + (b * NN + q0 + qq) * 64 + h * 16;
#pragma unroll
            for (int r = 0; r < 4; r++) {
                ulonglong2 o; o.x = acc[qq][2*r]; o.y = acc[qq][2*r+1];
                *(ulonglong2*)&op[r * 4] = o;
            }
        }
    }
}

// ---------------- 7) out projection y = y_attn @ out_w^T + out_b (FFMA2) ----------------
__global__ __launch_bounds__(256) void k_outp(const float* __restrict__ ow,
                                              const float* __restrict__ ob) {
    __shared__ float ysm[64 * 64];
    int t = threadIdx.x;
    int m0 = blockIdx.x * 64;
#pragma unroll
    for (int r = 0; r < 4; r++) {
        int idx = (t + 256 * r) * 4;
        *(float4*)&ysm[idx] = *(const float4*)&g_yattn[m0 * 64 + idx];
    }
    __syncthreads();
    int o = t & 63, gq = t >> 6;
    u64 wr[32];
#pragma unroll
    for (int r = 0; r < 16; r++) {
        ulonglong2 v = *(const ulonglong2*)&ow[o * 64 + r * 4];
        wr[2*r] = v.x; wr[2*r+1] = v.y;
    }
    float bias = ob[o];
    for (int rr = 0; rr < 16; rr++) {
        int mm = gq * 16 + rr;
        u64 a = 0;
#pragma unroll
        for (int r = 0; r < 16; r++) {
            ulonglong2 nv = *(ulonglong2*)&ysm[mm * 64 + r * 4];
            fma2(a, wr[2*r], nv.x);
            fma2(a, wr[2*r+1], nv.y);
        }
        g_y[(m0 + mm) * 64 + o] = hadd2(a) + bias;
    }
}

// ---------------- 8) adjacency mask bits: SINGLE pass + diagonal fixup ----------------
__global__ __launch_bounds__(256) void k_mask(const float* __restrict__ es) {
    __shared__ float ssm[32][36];
    __shared__ float dsm[2][64][36];
    __shared__ float diagsm[32];
    int t = threadIdx.x, w = t >> 5, lane = t & 31;
    int b = blockIdx.y;
    int q0 = blockIdx.x * 32;
    float scale = es[0];
    {
        int row = t >> 3, col = (t & 7) << 2;
        int q = q0 + row;
        float4 v = make_float4(0.f, 0.f, 0.f, 0.f);
        if (q < NN) v = *(const float4*)&g_src[(b * NN + q) * 32 + col];
        *(float4*)&ssm[row][col] = v;
    }
    int lrow0 = t >> 3, lcol0 = (t & 7) << 2;
    int lrow1 = (t + 256) >> 3, lcol1 = ((t + 256) & 7) << 2;
    auto prefetch = [&](int buf, int j0) {
        int r0 = j0 + lrow0; if (r0 > NN - 1) r0 = NN - 1;
        int r1 = j0 + lrow1; if (r1 > NN - 1) r1 = NN - 1;
        cp_async16(&dsm[buf][lrow0][lcol0], &g_dst[(b * NN + r0) * 32 + lcol0]);
        cp_async16(&dsm[buf][lrow1][lcol1], &g_dst[(b * NN + r1) * 32 + lcol1]);
    };
    __syncthreads();
    u64 qu[4][16];
#pragma unroll
    for (int c = 0; c < 4; c++) {
#pragma unroll
        for (int r = 0; r < 8; r++) {
            ulonglong2 v = *(ulonglong2*)&ssm[w * 4 + c][r * 4];
            qu[c][2*r] = v.x; qu[c][2*r+1] = v.y;
        }
    }

    const int NJT = 32;
    prefetch(0, 0); cp_commit();
    float sumsq[4] = {};
    for (int jt = 0; jt < NJT; jt++) {
        int j0 = jt * 64;
        if (jt + 1 < NJT) { prefetch((jt + 1) & 1, j0 + 64); cp_commit(); cp_wait<1>(); }
        else              { cp_wait<0>(); }
        __syncthreads();
        int buf = jt & 1;
#pragma unroll
        for (int half = 0; half < 2; half++) {
            int jj = lane + 32 * half;
            u64 dv[16];
#pragma unroll
            for (int r = 0; r < 8; r++) {
                ulonglong2 v = *(ulonglong2*)&dsm[buf][jj][r * 4];
                dv[2*r] = v.x; dv[2*r+1] = v.y;
            }
            bool valid = (j0 + jj < NN);
#pragma unroll
            for (int c = 0; c < 4; c++) {
                int q = q0 + w * 4 + c;
                u64 a = 0;
#pragma unroll
                for (int r = 0; r < 16; r++) fma2(a, qu[c][r], dv[r]);
                float s = hadd2(a);
                unsigned word = __ballot_sync(0xffffffffu, s * scale <= 0.f);
                if (lane == 0 && q < NN) g_maskbits[(b * NN + q) * 64 + jt * 2 + half] = word;
                if (valid) sumsq[c] += s * s;
                if (j0 + jj == q) diagsm[w * 4 + c] = s;
            }
        }
        __syncthreads();
    }
#pragma unroll
    for (int c = 0; c < 4; c++) {
        float red = sumsq[c];
#pragma unroll
        for (int off = 16; off; off >>= 1) red += __shfl_xor_sync(0xffffffffu, red, off);
        if (lane == 0) {
            int qq = w * 4 + c;
            int q = q0 + qq;
            if (q < NN) {
                float norm = fmaxf(sqrtf(red) * fabsf(scale), 1e-12f);
                float sd = diagsm[qq];
                bool bit = (sd * scale <= -norm);
                unsigned idx = (b * NN + q) * 64 + (q >> 5);
                unsigned word = g_maskbits[idx];
                unsigned msk = 1u << (q & 31);
                g_maskbits[idx] = bit ? (word | msk) : (word & ~msk);
            }
        }
    }
}

// ---------------- 9) attention-2: 4 queries/warp, dim-split PV, FFMA2 ----------------
// 128 threads = 4 warps, 16 queries per block. Each V-row quarter read feeds 4 queries.
__global__ __launch_bounds__(128) void k_attn2() {
    __shared__ float ysm[2][64][68];
    __shared__ float qsm[16][68];
    __shared__ float psm[4][4][64];
    int t = threadIdx.x, w = t >> 5, lane = t & 31;
    int b = blockIdx.y;
    int qbase = blockIdx.x * 16;
    int q0 = qbase + w * 4;
    const float* yb = g_y + b * (NN * 64);
    const unsigned* mrow0 = g_maskbits + (b * NN + q0) * 64;
    const unsigned* mrow1 = mrow0 + 64;
    const unsigned* mrow2 = mrow0 + 128;
    const unsigned* mrow3 = mrow0 + 192;
    // load 16 query rows (8 floats per thread)
    {
        int row = t >> 3, col = (t & 7) * 8;
        *(float4*)&qsm[row][col]     = *(const float4*)&yb[(qbase + row) * 64 + col];
        *(float4*)&qsm[row][col + 4] = *(const float4*)&yb[(qbase + row) * 64 + col + 4];
    }

    int prow = t >> 4, pcol = (t & 15) << 2;
    auto prefetch = [&](int buf, int j0) {
#pragma unroll
        for (int r = 0; r < 8; r++) {
            int row = prow + 8 * r;
            int grow = j0 + row; if (grow > NN - 1) grow = NN - 1;
            cp_async16(&ysm[buf][row][pcol], &yb[grow * 64 + pcol]);
        }
    };

    const int NT = (NN + 63) / 64;  // 32
    prefetch(0, 0); cp_commit();

    float mx[4] = {-1e30f, -1e30f, -1e30f, -1e30f};
    float l[4] = {};
    u64 accP[4][8] = {};          // [query][8 u64 = 16 dims at dq*16]
    int kg = lane & 7, dq = lane >> 3;

    for (int it = 0; it < NT; it++) {
        int j0 = it * 64;
        if (it + 1 < NT) { prefetch((it + 1) & 1, j0 + 64); cp_commit(); cp_wait<1>(); }
        else             { cp_wait<0>(); }
        __syncthreads();
        int buf = it & 1;
        // ---- scores: lane covers keys (lane, lane+32) for 4 queries ----
        u64 S[4][2] = {};
#pragma unroll
        for (int r = 0; r < 16; r++) {
            ulonglong2 k0 = *(ulonglong2*)&ysm[buf][lane][r * 4];
            ulonglong2 k1 = *(ulonglong2*)&ysm[buf][lane + 32][r * 4];
#pragma unroll
            for (int qq = 0; qq < 4; qq++) {
                ulonglong2 qv = *(ulonglong2*)&qsm[w * 4 + qq][r * 4];
                fma2(S[qq][0], qv.x, k0.x); fma2(S[qq][0], qv.y, k0.y);
                fma2(S[qq][1], qv.x, k1.x); fma2(S[qq][1], qv.y, k1.y);
            }
        }
        bool oob0 = (j0 + lane >= NN), oob1 = (j0 + 32 + lane >= NN);
        const unsigned* mr[4] = {mrow0, mrow1, mrow2, mrow3};
#pragma unroll
        for (int qq = 0; qq < 4; qq++) {
            float s0 = hadd2(S[qq][0]) * 0.125f + (((mr[qq][it * 2]     >> lane) & 1u) ? -1e9f : 0.f);
            float s1 = hadd2(S[qq][1]) * 0.125f + (((mr[qq][it * 2 + 1] >> lane) & 1u) ? -1e9f : 0.f);
            if (oob0) s0 = -1e30f;
            if (oob1) s1 = -1e30f;
            float tm = fmaxf(s0, s1);
#pragma unroll
            for (int off = 16; off; off >>= 1) tm = fmaxf(tm, __shfl_xor_sync(0xffffffffu, tm, off));
            if (tm > mx[qq]) {
                float f = __expf(mx[qq] - tm);
                l[qq] *= f;
                u64 f2 = pack2(f);
#pragma unroll
                for (int r = 0; r < 8; r++) mul2(accP[qq][r], f2);
                mx[qq] = tm;
            }
            float p0 = __expf(s0 - mx[qq]);
            float p1 = __expf(s1 - mx[qq]);
            l[qq] += p0 + p1;
            psm[w][qq][lane]      = p0;
            psm[w][qq][lane + 32] = p1;
        }
        __syncwarp();
        // ---- PV: lane = (key-group kg, dim-quarter dq); 8 keys x 16 dims x 4 queries ----
#pragma unroll
        for (int c = 0; c < 8; c++) {
            int j = kg + 8 * c;
            const float* vrow = &ysm[buf][j][dq * 16];
            ulonglong2 va = *(ulonglong2*)&vrow[0];
            ulonglong2 vb = *(ulonglong2*)&vrow[4];
            ulonglong2 vc = *(ulonglong2*)&vrow[8];
            ulonglong2 vd = *(ulonglong2*)&vrow[12];
            u64 v[8] = {va.x, va.y, vb.x, vb.y, vc.x, vc.y, vd.x, vd.y};
#pragma unroll
            for (int qq = 0; qq < 4; qq++) {
                u64 p2 = pack2(psm[w][qq][j]);
#pragma unroll
                for (int r = 0; r < 8; r++) fma2(accP[qq][r], p2, v[r]);
            }
        }
        __syncthreads();
    }
    // ---- normalizers ----
#pragma unroll
    for (int qq = 0; qq < 4; qq++) {
#pragma unroll
        for (int off = 16; off; off >>= 1) l[qq] += __shfl_xor_sync(0xffffffffu, l[qq], off);
    }
    // ---- butterfly over kg bits (1,2,4): sum key-group partials ----
#pragma unroll
    for (int off = 1; off <= 4; off <<= 1) {
#pragma unroll
        for (int qq = 0; qq < 4; qq++) {
#pragma unroll
            for (int r = 0; r < 8; r++) {
                u64 o = __shfl_xor_sync(0xffffffffu, accP[qq][r], off);
                add2(accP[qq][r], o);
            }
        }
    }
    // lanes with kg<4 write query kg, dims [dq*16, dq*16+16)
    if (kg < 4) {
        int qq = kg;
        u64 i2 = pack2(1.f / l[qq]);
        float* op = &g_y2[(b * NN + q0 + qq) * 64 + dq * 16];
#pragma unroll
        for (int r = 0; r < 8; r++) mul2(accP[qq][r], i2);
#pragma unroll
        for (int k = 0; k < 4; k++) {
            ulonglong2 o; o.x = accP[qq][2 * k]; o.y = accP[qq][2 * k + 1];
            *(ulonglong2*)&op[4 * k] = o;
        }
    }
}

// ---------------- 10) residual + LN(lnA) + horizon predictor ----------------
__global__ __launch_bounds__(256) void k_final(const float* __restrict__ lg,
                                               const float* __restrict__ lb,
                                               const float* __restrict__ pw,
                                               const float* __restrict__ pb,
                                               float* __restrict__ out) {
    __shared__ float rsm[8][64];
    __shared__ float pwsm[64 * 24];
    int t = threadIdx.x, w = t >> 5, lane = t & 31;
    int m = blockIdx.x * 8 + w;
    for (int idx = t; idx < 24 * 64; idx += 256) {
        int o = idx >> 6, d = idx & 63;
        pwsm[d * 24 + o] = pw[idx];
    }
    float v0 = g_y2[m * 64 + lane]      + g_node[m * 64 + lane];
    float v1 = g_y2[m * 64 + 32 + lane] + g_node[m * 64 + 32 + lane];
    float s = v0 + v1;
#pragma unroll
    for (int off = 16; off; off >>= 1) s += __shfl_xor_sync(0xffffffffu, s, off);
    float mean = s * (1.f / 64.f);
    float d0 = v0 - mean, d1 = v1 - mean;
    float vs = d0 * d0 + d1 * d1;
#pragma unroll
    for (int off = 16; off; off >>= 1) vs += __shfl_xor_sync(0xffffffffu, vs, off);
    float rs = rsqrtf(vs * (1.f / 64.f) + 1e-5f);
    rsm[w][lane]      = d0 * rs * lg[lane]      + lb[lane];
    rsm[w][lane + 32] = d1 * rs * lg[lane + 32] + lb[lane + 32];
    __syncthreads();
    if (lane < 24) {
        float acc = pb[lane];
#pragma unroll
        for (int d = 0; d < 64; d++) acc += rsm[w][d] * pwsm[d * 24 + lane];
        out[m * 24 + lane] = acc;
    }
}

// ---------------- launch ----------------
extern "C" void kernel_launch(void* const* d_in, const int* in_sizes, int n_in,
                              void* d_out, int out_size) {
    const float* x        = (const float*)d_in[0];
    const float* conv_w   = (const float*)d_in[1];
    const float* conv_b   = (const float*)d_in[2];
    const float* bn_g     = (const float*)d_in[3];
    const float* bn_b     = (const float*)d_in[4];
    const float* proj_w   = (const float*)d_in[5];
    const float* proj_b   = (const float*)d_in[6];
    const float* ln1_g    = (const float*)d_in[7];
    const float* ln1_b    = (const float*)d_in[8];
    const float* src_w    = (const float*)d_in[9];
    const float* src_b    = (const float*)d_in[10];
    const float* dst_w    = (const float*)d_in[11];
    const float* dst_b    = (const float*)d_in[12];
    const float* edge_sc  = (const float*)d_in[13];
    const float* inp_w    = (const float*)d_in[14];
    const float* inp_b    = (const float*)d_in[15];
    const float* out_w    = (const float*)d_in[16];
    const float* out_b    = (const float*)d_in[17];
    const float* lnA_g    = (const float*)d_in[18];
    const float* lnA_b    = (const float*)d_in[19];
    const float* pred_w   = (const float*)d_in[20];
    const float* pred_b   = (const float*)d_in[21];
    float* out = (float*)d_out;

    k_conv<<<dim3((BN + 255) / 256, TT), 256>>>(x, conv_w, conv_b, bn_g, bn_b);
    k_transw<<<(FT * HH + 255) / 256, 256>>>(proj_w);
    k_proj<<<BN / 64, 256>>>(proj_b);
    k_ln1<<<BN / 8, 256>>>(ln1_g, ln1_b);
    k_sdq<<<BN / 64, 256>>>(src_w, src_b, dst_w, dst_b, inp_w, inp_b);
    k_attn1<<<dim3(NN / 16, NHEADS, BB), 128>>>();
    k_outp<<<BN / 64, 256>>>(out_w, out_b);
    k_mask<<<dim3((NN + 31) / 32, BB), 256>>>(edge_sc);
    k_attn2<<<dim3(NN / 16, BB), 128>>>();
    k_final<<<BN / 8, 256>>>(lnA_g, lnA_b, pred_w, pred_b, out);
}